// round 2
// baseline (speedup 1.0000x reference)
#include <cuda_runtime.h>
#include <math.h>

#define N_TOK     4096
#define HIDDEN    1152
#define NUM_HEADS 16
#define HEAD_DIM  72
#define PROJ      1152   // NUM_HEADS * HEAD_DIM

// Scratch (device globals: allocation-free per harness rules)
__device__ float g_q[(size_t)N_TOK * PROJ];
__device__ float g_k[(size_t)N_TOK * PROJ];
__device__ float g_v[(size_t)N_TOK * PROJ];
__device__ float g_o[(size_t)N_TOK * PROJ];

// ---------------------------------------------------------------------------
// Tiled fp32 GEMM: C[M,N] = A[M,K] @ B[K,N], all row-major.
// BM=BN=64, BK=16, 256 threads, 4x4 micro-tile per thread.
// M%64==0, N%64==0, K%16==0 hold for every call here (4096/1152/1152).
// ---------------------------------------------------------------------------
__global__ void __launch_bounds__(256) gemm_kernel(
    const float* __restrict__ A, const float* __restrict__ B, float* __restrict__ C,
    int M, int N, int K)
{
    __shared__ float As[16][64];
    __shared__ float Bs[16][64];

    const int tid  = threadIdx.x;
    const int row0 = blockIdx.y * 64;
    const int col0 = blockIdx.x * 64;
    const int tx = tid & 15, ty = tid >> 4;

    const int aRow = tid >> 2;          // 0..63
    const int aCol = (tid & 3) << 2;    // 0,4,8,12
    const int bRow = tid >> 4;          // 0..15
    const int bCol = (tid & 15) << 2;   // 0..60

    float acc[4][4];
    #pragma unroll
    for (int i = 0; i < 4; i++)
        #pragma unroll
        for (int j = 0; j < 4; j++) acc[i][j] = 0.f;

    for (int k0 = 0; k0 < K; k0 += 16) {
        float4 a4 = *(const float4*)(A + (size_t)(row0 + aRow) * K + k0 + aCol);
        float4 b4 = *(const float4*)(B + (size_t)(k0 + bRow) * N + col0 + bCol);
        __syncthreads();
        As[aCol + 0][aRow] = a4.x;
        As[aCol + 1][aRow] = a4.y;
        As[aCol + 2][aRow] = a4.z;
        As[aCol + 3][aRow] = a4.w;
        *(float4*)&Bs[bRow][bCol] = b4;
        __syncthreads();

        #pragma unroll
        for (int kk = 0; kk < 16; kk++) {
            float a0 = As[kk][ty * 4 + 0];
            float a1 = As[kk][ty * 4 + 1];
            float a2 = As[kk][ty * 4 + 2];
            float a3 = As[kk][ty * 4 + 3];
            float4 b = *(float4*)&Bs[kk][tx * 4];
            acc[0][0] += a0 * b.x; acc[0][1] += a0 * b.y; acc[0][2] += a0 * b.z; acc[0][3] += a0 * b.w;
            acc[1][0] += a1 * b.x; acc[1][1] += a1 * b.y; acc[1][2] += a1 * b.z; acc[1][3] += a1 * b.w;
            acc[2][0] += a2 * b.x; acc[2][1] += a2 * b.y; acc[2][2] += a2 * b.z; acc[2][3] += a2 * b.w;
            acc[3][0] += a3 * b.x; acc[3][1] += a3 * b.y; acc[3][2] += a3 * b.z; acc[3][3] += a3 * b.w;
        }
    }

    #pragma unroll
    for (int i = 0; i < 4; i++) {
        float4 r = make_float4(acc[i][0], acc[i][1], acc[i][2], acc[i][3]);
        *(float4*)(C + (size_t)(row0 + ty * 4 + i) * N + col0 + tx * 4) = r;
    }
}

// ---------------------------------------------------------------------------
// Fused RMSNorm + 2D RoPE. One warp per (token, head) row of 72 elems.
// q: rmsnorm(w=q_scale)+rope, k: rmsnorm(w=k_scale)+rope, v: rmsnorm only.
// In-place on g_q/g_k/g_v.
// ---------------------------------------------------------------------------
__device__ __forceinline__ float warp_sum(float v) {
    #pragma unroll
    for (int o = 16; o > 0; o >>= 1) v += __shfl_xor_sync(0xffffffffu, v, o);
    return v;
}

__global__ void __launch_bounds__(256) normrope_kernel(
    const float* __restrict__ cosp, const float* __restrict__ sinp,
    const float* __restrict__ qscale, const float* __restrict__ kscale)
{
    __shared__ float buf[8][72];
    const int warp = threadIdx.x >> 5;
    const int lane = threadIdx.x & 31;
    const int gw = blockIdx.x * 8 + warp;          // 0 .. N_TOK*NUM_HEADS-1
    const int n = gw >> 4;
    const int h = gw & 15;
    const size_t off = (size_t)n * PROJ + h * HEAD_DIM;
    const float* crow = cosp + (size_t)n * HEAD_DIM;
    const float* srow = sinp + (size_t)n * HEAD_DIM;

    float* bufs[3] = { g_q + off, g_k + off, g_v + off };

    for (int w = 0; w < 3; w++) {
        float* p = bufs[w];
        float ss = 0.f;
        for (int d = lane; d < HEAD_DIM; d += 32) {
            float x = p[d];
            buf[warp][d] = x;
            ss += x * x;
        }
        ss = warp_sum(ss);
        float r = rsqrtf(ss * (1.f / HEAD_DIM) + 1e-6f);
        __syncwarp();
        for (int d = lane; d < HEAD_DIM; d += 32) {
            float y = buf[warp][d] * r;
            if (w == 0)      y *= qscale[d];
            else if (w == 1) y *= kscale[d];
            buf[warp][d] = y;
        }
        __syncwarp();
        if (w < 2) {
            for (int d = lane; d < HEAD_DIM; d += 32) {
                int j = (d < 36) ? d : d - 36;         // position within half
                float rot = (j < 18) ? -buf[warp][d + 18] : buf[warp][d - 18];
                p[d] = buf[warp][d] * crow[d] + rot * srow[d];
            }
        } else {
            for (int d = lane; d < HEAD_DIM; d += 32) p[d] = buf[warp][d];
        }
        __syncwarp();
    }
}

// ---------------------------------------------------------------------------
// Flash attention (non-causal, no scale factor — matches the reference).
// Grid: (head, qtile). 64 queries/block, 64-key tiles, 128 threads.
// Thread pair (2 per query row): each owns 32 score cols / 36 output dims.
// ---------------------------------------------------------------------------
#define TQ 64
#define TK 64
#define KS_STRIDE 74              // even (float2-able), reads are broadcast anyway
#define QS_FLOATS (TQ * 72)
#define KS_FLOATS (TK * KS_STRIDE)
#define SS_STRIDE 65
#define SS_FLOATS (TQ * SS_STRIDE)
#define ATTN_SMEM_BYTES ((QS_FLOATS + 2 * KS_FLOATS + SS_FLOATS) * 4)

__global__ void __launch_bounds__(128) attn_kernel(
    const float* __restrict__ Q, const float* __restrict__ K,
    const float* __restrict__ V, float* __restrict__ O)
{
    extern __shared__ float sm[];
    float* Qs = sm;                          // [TQ][72]
    float* Ks = Qs + QS_FLOATS;              // [TK][74]
    float* Vs = Ks + KS_FLOATS;              // [TK][74]
    float* Ss = Vs + KS_FLOATS;              // [TQ][65]

    const int h    = blockIdx.x;
    const int q0   = blockIdx.y * TQ;
    const int tid  = threadIdx.x;
    const int row  = tid >> 1;               // 0..63
    const int half = tid & 1;                // 0/1
    const int hoff = h * HEAD_DIM;

    // Load Q tile
    for (int idx = tid; idx < TQ * 72; idx += 128) {
        int r = idx / 72, d = idx - r * 72;
        Qs[idx] = Q[(size_t)(q0 + r) * PROJ + hoff + d];
    }

    float m = -1e30f, l = 0.f;
    float acc[36];
    #pragma unroll
    for (int j = 0; j < 36; j++) acc[j] = 0.f;

    const float* qrow  = Qs + row * 72;
    const float* kbase = Ks + (half * 32) * KS_STRIDE;

    for (int k0 = 0; k0 < N_TOK; k0 += TK) {
        __syncthreads();   // previous tile fully consumed
        for (int idx = tid; idx < TK * 72; idx += 128) {
            int r = idx / 72, d = idx - r * 72;
            size_t g = (size_t)(k0 + r) * PROJ + hoff + d;
            Ks[r * KS_STRIDE + d] = K[g];
            Vs[r * KS_STRIDE + d] = V[g];
        }
        __syncthreads();

        // Scores: 32 per thread (keys half*32 .. half*32+31)
        float s[32];
        #pragma unroll
        for (int kk = 0; kk < 32; kk++) s[kk] = 0.f;
        for (int d = 0; d < 72; d += 2) {
            float2 q2 = *(const float2*)(qrow + d);
            #pragma unroll
            for (int kk = 0; kk < 32; kk++) {
                float2 k2 = *(const float2*)(kbase + kk * KS_STRIDE + d);
                s[kk] += q2.x * k2.x + q2.y * k2.y;
            }
        }

        // Online softmax update (pair shares state via shfl)
        float mt = s[0];
        #pragma unroll
        for (int kk = 1; kk < 32; kk++) mt = fmaxf(mt, s[kk]);
        mt = fmaxf(mt, __shfl_xor_sync(0xffffffffu, mt, 1));
        float mnew = fmaxf(m, mt);
        float corr = __expf(m - mnew);
        float lsum = 0.f;
        #pragma unroll
        for (int kk = 0; kk < 32; kk++) {
            s[kk] = __expf(s[kk] - mnew);
            lsum += s[kk];
        }
        lsum += __shfl_xor_sync(0xffffffffu, lsum, 1);
        l = l * corr + lsum;
        m = mnew;
        #pragma unroll
        for (int j = 0; j < 36; j++) acc[j] *= corr;

        // Publish P for the row, then accumulate P @ V over all 64 keys
        __syncwarp();
        #pragma unroll
        for (int kk = 0; kk < 32; kk++)
            Ss[row * SS_STRIDE + half * 32 + kk] = s[kk];
        __syncwarp();

        const float* vcol = Vs + half * 36;
        for (int k = 0; k < TK; k++) {
            float p = Ss[row * SS_STRIDE + k];
            const float* vr = vcol + k * KS_STRIDE;
            #pragma unroll
            for (int j = 0; j < 36; j += 2) {
                float2 v2 = *(const float2*)(vr + j);
                acc[j]     += p * v2.x;
                acc[j + 1] += p * v2.y;
            }
        }
    }

    float inv = 1.f / l;
    float* orow = O + (size_t)(q0 + row) * PROJ + hoff + half * 36;
    #pragma unroll
    for (int j = 0; j < 36; j++) orow[j] = acc[j] * inv;
}

// ---------------------------------------------------------------------------
extern "C" void kernel_launch(void* const* d_in, const int* in_sizes, int n_in,
                              void* d_out, int out_size)
{
    const float* hidden = (const float*)d_in[0];
    const float* cosp   = (const float*)d_in[1];
    const float* sinp   = (const float*)d_in[2];
    const float* Wq     = (const float*)d_in[3];
    const float* Wk     = (const float*)d_in[4];
    const float* Wv     = (const float*)d_in[5];
    const float* Wo     = (const float*)d_in[6];
    const float* qsc    = (const float*)d_in[7];
    const float* ksc    = (const float*)d_in[8];
    float* out = (float*)d_out;

    float *q, *k, *v, *o;
    cudaGetSymbolAddress((void**)&q, g_q);
    cudaGetSymbolAddress((void**)&k, g_k);
    cudaGetSymbolAddress((void**)&v, g_v);
    cudaGetSymbolAddress((void**)&o, g_o);

    dim3 gg(PROJ / 64, N_TOK / 64);
    gemm_kernel<<<gg, 256>>>(hidden, Wq, q, N_TOK, PROJ, HIDDEN);
    gemm_kernel<<<gg, 256>>>(hidden, Wk, k, N_TOK, PROJ, HIDDEN);
    gemm_kernel<<<gg, 256>>>(hidden, Wv, v, N_TOK, PROJ, HIDDEN);

    normrope_kernel<<<(N_TOK * NUM_HEADS) / 8, 256>>>(cosp, sinp, qsc, ksc);

    cudaFuncSetAttribute(attn_kernel,
                         cudaFuncAttributeMaxDynamicSharedMemorySize,
                         ATTN_SMEM_BYTES);
    attn_kernel<<<dim3(NUM_HEADS, N_TOK / TQ), 128, ATTN_SMEM_BYTES>>>(q, k, v, o);

    gemm_kernel<<<gg, 256>>>(o, Wo, out, N_TOK, HIDDEN, PROJ);
}

// round 3
// speedup vs baseline: 2.0502x; 2.0502x over previous
#include <cuda_runtime.h>
#include <math.h>

#define N_TOK     4096
#define HIDDEN    1152
#define NUM_HEADS 16
#define HEAD_DIM  72
#define PROJ      1152   // NUM_HEADS * HEAD_DIM

// Scratch (device globals: allocation-free per harness rules)
__device__ float g_q[(size_t)N_TOK * PROJ];
__device__ float g_k[(size_t)N_TOK * PROJ];
__device__ float g_v[(size_t)N_TOK * PROJ];
__device__ float g_o[(size_t)N_TOK * PROJ];

// ---------------------------------------------------------------------------
// tf32 helpers
// ---------------------------------------------------------------------------
__device__ __forceinline__ unsigned f2tf(float x) {
    unsigned u;
    asm("cvt.rna.tf32.f32 %0, %1;" : "=r"(u) : "f"(x));
    return u;
}
__device__ __forceinline__ float uif(unsigned u) { return __uint_as_float(u); }

// D += A*B  (m16n8k8 tf32, row.col)
__device__ __forceinline__ void mma8(float c[4], const unsigned a[4], const unsigned b[2]) {
    asm("mma.sync.aligned.m16n8k8.row.col.f32.tf32.tf32.f32 "
        "{%0,%1,%2,%3},{%4,%5,%6,%7},{%8,%9},{%0,%1,%2,%3};"
        : "+f"(c[0]), "+f"(c[1]), "+f"(c[2]), "+f"(c[3])
        : "r"(a[0]), "r"(a[1]), "r"(a[2]), "r"(a[3]), "r"(b[0]), "r"(b[1]));
}

// ---------------------------------------------------------------------------
// tf32x3 GEMM: C[M,N] = A[M,K] @ B[K,N], row-major. Block 128x128, BK=8,
// 8 warps, each warp 64x32 (4 m-tiles x 4 n-tiles of m16n8).
// Requires M%128==0, N%128==0, K%8==0 (true for all calls: 4096/1152).
// ---------------------------------------------------------------------------
__global__ void __launch_bounds__(256) gemm_x3_kernel(
    const float* __restrict__ A, const float* __restrict__ B, float* __restrict__ C,
    int M, int N, int K)
{
    __shared__ unsigned Ah[8][136], Al[8][136];   // [k][m], pad 136 (8 banks apart per k)
    __shared__ unsigned Bh[8][136], Bl[8][136];   // [k][n]

    const int tid  = threadIdx.x;
    const int lane = tid & 31;
    const int wid  = tid >> 5;
    const int row0 = blockIdx.y * 128;
    const int col0 = blockIdx.x * 128;
    const int warpM = (wid & 1) * 64;
    const int warpN = (wid >> 1) * 32;
    const int g  = lane >> 2;   // group id (row within tile)
    const int tg = lane & 3;    // thread in group (k / col pairs)

    // global load mapping
    const int aRow = tid >> 1;          // 0..127
    const int aC   = (tid & 1) * 4;     // 0 or 4
    const int bRow = tid >> 5;          // 0..7
    const int bC   = (tid & 31) * 4;    // 0..124

    float acc[4][4][4];
    #pragma unroll
    for (int mt = 0; mt < 4; mt++)
        #pragma unroll
        for (int nt = 0; nt < 4; nt++)
            #pragma unroll
            for (int r = 0; r < 4; r++) acc[mt][nt][r] = 0.f;

    float4 a4 = *(const float4*)(A + (size_t)(row0 + aRow) * K + aC);
    float4 b4 = *(const float4*)(B + (size_t)bRow * N + col0 + bC);

    for (int k0 = 0; k0 < K; k0 += 8) {
        __syncthreads();
        // convert + store current k-slab
        {
            float av[4] = {a4.x, a4.y, a4.z, a4.w};
            #pragma unroll
            for (int j = 0; j < 4; j++) {
                unsigned h = f2tf(av[j]);
                Ah[aC + j][aRow] = h;
                Al[aC + j][aRow] = f2tf(av[j] - uif(h));
            }
            float bv[4] = {b4.x, b4.y, b4.z, b4.w};
            uint4 hh, ll;
            unsigned* hp = &hh.x; unsigned* lp = &ll.x;
            #pragma unroll
            for (int j = 0; j < 4; j++) {
                unsigned h = f2tf(bv[j]);
                hp[j] = h;
                lp[j] = f2tf(bv[j] - uif(h));
            }
            *(uint4*)&Bh[bRow][bC] = hh;
            *(uint4*)&Bl[bRow][bC] = ll;
        }
        __syncthreads();

        // prefetch next slab
        if (k0 + 8 < K) {
            a4 = *(const float4*)(A + (size_t)(row0 + aRow) * K + (k0 + 8) + aC);
            b4 = *(const float4*)(B + (size_t)(k0 + 8 + bRow) * N + col0 + bC);
        }

        // fragments
        unsigned ah[4][4], al[4][4], bh[4][2], bl[4][2];
        #pragma unroll
        for (int mt = 0; mt < 4; mt++) {
            int m = warpM + mt * 16 + g;
            ah[mt][0] = Ah[tg][m];     ah[mt][1] = Ah[tg][m + 8];
            ah[mt][2] = Ah[tg + 4][m]; ah[mt][3] = Ah[tg + 4][m + 8];
            al[mt][0] = Al[tg][m];     al[mt][1] = Al[tg][m + 8];
            al[mt][2] = Al[tg + 4][m]; al[mt][3] = Al[tg + 4][m + 8];
        }
        #pragma unroll
        for (int nt = 0; nt < 4; nt++) {
            int n = warpN + nt * 8 + g;
            bh[nt][0] = Bh[tg][n]; bh[nt][1] = Bh[tg + 4][n];
            bl[nt][0] = Bl[tg][n]; bl[nt][1] = Bl[tg + 4][n];
        }
        #pragma unroll
        for (int mt = 0; mt < 4; mt++)
            #pragma unroll
            for (int nt = 0; nt < 4; nt++) {
                mma8(acc[mt][nt], ah[mt], bh[nt]);   // hi*hi
                mma8(acc[mt][nt], ah[mt], bl[nt]);   // hi*lo
                mma8(acc[mt][nt], al[mt], bh[nt]);   // lo*hi
            }
    }

    #pragma unroll
    for (int mt = 0; mt < 4; mt++)
        #pragma unroll
        for (int nt = 0; nt < 4; nt++) {
            int r = row0 + warpM + mt * 16 + g;
            int c = col0 + warpN + nt * 8 + 2 * tg;
            float2 v0 = make_float2(acc[mt][nt][0], acc[mt][nt][1]);
            float2 v1 = make_float2(acc[mt][nt][2], acc[mt][nt][3]);
            *(float2*)(C + (size_t)r * N + c)       = v0;
            *(float2*)(C + (size_t)(r + 8) * N + c) = v1;
        }
}

// ---------------------------------------------------------------------------
// Fused RMSNorm + 2D RoPE (unchanged from R2; 47us, not on the critical path)
// ---------------------------------------------------------------------------
__device__ __forceinline__ float warp_sum(float v) {
    #pragma unroll
    for (int o = 16; o > 0; o >>= 1) v += __shfl_xor_sync(0xffffffffu, v, o);
    return v;
}

__global__ void __launch_bounds__(256) normrope_kernel(
    const float* __restrict__ cosp, const float* __restrict__ sinp,
    const float* __restrict__ qscale, const float* __restrict__ kscale)
{
    __shared__ float buf[8][72];
    const int warp = threadIdx.x >> 5;
    const int lane = threadIdx.x & 31;
    const int gw = blockIdx.x * 8 + warp;
    const int n = gw >> 4;
    const int h = gw & 15;
    const size_t off = (size_t)n * PROJ + h * HEAD_DIM;
    const float* crow = cosp + (size_t)n * HEAD_DIM;
    const float* srow = sinp + (size_t)n * HEAD_DIM;

    float* bufs[3] = { g_q + off, g_k + off, g_v + off };

    for (int w = 0; w < 3; w++) {
        float* p = bufs[w];
        float ss = 0.f;
        for (int d = lane; d < HEAD_DIM; d += 32) {
            float x = p[d];
            buf[warp][d] = x;
            ss += x * x;
        }
        ss = warp_sum(ss);
        float r = rsqrtf(ss * (1.f / HEAD_DIM) + 1e-6f);
        __syncwarp();
        for (int d = lane; d < HEAD_DIM; d += 32) {
            float y = buf[warp][d] * r;
            if (w == 0)      y *= qscale[d];
            else if (w == 1) y *= kscale[d];
            buf[warp][d] = y;
        }
        __syncwarp();
        if (w < 2) {
            for (int d = lane; d < HEAD_DIM; d += 32) {
                int j = (d < 36) ? d : d - 36;
                float rot = (j < 18) ? -buf[warp][d + 18] : buf[warp][d - 18];
                p[d] = buf[warp][d] * crow[d] + rot * srow[d];
            }
        } else {
            for (int d = lane; d < HEAD_DIM; d += 32) p[d] = buf[warp][d];
        }
        __syncwarp();
    }
}

// ---------------------------------------------------------------------------
// Flash attention with tf32x3 tensor-core mma.
// Block = (head, 64-query tile), 4 warps; warp w owns S/O rows 16w..16w+15.
// K tile staged as [key][d] stride 76 (all-distinct banks for B fragments),
// V as [key][d] stride 72, P as [row][key] stride 76.
// ---------------------------------------------------------------------------
#define KST 76
#define VST 72
#define PST 76
#define SM_KS  (64 * KST)
#define SM_VS  (64 * VST)
#define SM_PS  (64 * PST)
#define ATTN_SMEM_BYTES ((2 * SM_KS + 2 * SM_VS + 2 * SM_PS) * 4)

__global__ void __launch_bounds__(128) attn_mma_kernel(
    const float* __restrict__ Q, const float* __restrict__ K,
    const float* __restrict__ V, float* __restrict__ O)
{
    extern __shared__ unsigned sm[];
    unsigned* Ksh = sm;
    unsigned* Ksl = Ksh + SM_KS;
    unsigned* Vsh = Ksl + SM_KS;
    unsigned* Vsl = Vsh + SM_VS;
    unsigned* Psh = Vsl + SM_VS;
    unsigned* Psl = Psh + SM_PS;
    float* Qs = (float*)Psh;   // staging alias (row region is warp-private later)

    const int h    = blockIdx.x;
    const int q0   = blockIdx.y * 64;
    const int tid  = threadIdx.x;
    const int lane = tid & 31;
    const int w    = tid >> 5;
    const int g    = lane >> 2;
    const int tg   = lane & 3;
    const int hoff = h * HEAD_DIM;
    const int arow = w * 16 + g;     // first S-row this thread touches

    // ---- stage Q tile and extract per-warp A fragments (hi/lo) ----
    for (int it = tid; it < 64 * 18; it += 128) {
        int r = it / 18, dq = (it % 18) * 4;
        float4 v = *(const float4*)(Q + (size_t)(q0 + r) * PROJ + hoff + dq);
        Qs[r * PST + dq + 0] = v.x;
        Qs[r * PST + dq + 1] = v.y;
        Qs[r * PST + dq + 2] = v.z;
        Qs[r * PST + dq + 3] = v.w;
    }
    __syncthreads();

    unsigned qh[9][4], ql[9][4];
    #pragma unroll
    for (int kt = 0; kt < 9; kt++) {
        float x0 = Qs[(arow)     * PST + kt * 8 + tg];
        float x1 = Qs[(arow + 8) * PST + kt * 8 + tg];
        float x2 = Qs[(arow)     * PST + kt * 8 + tg + 4];
        float x3 = Qs[(arow + 8) * PST + kt * 8 + tg + 4];
        qh[kt][0] = f2tf(x0); ql[kt][0] = f2tf(x0 - uif(qh[kt][0]));
        qh[kt][1] = f2tf(x1); ql[kt][1] = f2tf(x1 - uif(qh[kt][1]));
        qh[kt][2] = f2tf(x2); ql[kt][2] = f2tf(x2 - uif(qh[kt][2]));
        qh[kt][3] = f2tf(x3); ql[kt][3] = f2tf(x3 - uif(qh[kt][3]));
    }
    __syncthreads();   // Q reads done before Ps writes anywhere

    float m0 = -1e30f, m1 = -1e30f, l0 = 0.f, l1 = 0.f;
    float o[9][4];
    #pragma unroll
    for (int nt = 0; nt < 9; nt++)
        #pragma unroll
        for (int r = 0; r < 4; r++) o[nt][r] = 0.f;

    for (int k0 = 0; k0 < N_TOK; k0 += 64) {
        __syncthreads();   // previous tile fully consumed
        // ---- load K,V tile, split hi/lo ----
        for (int it = tid; it < 64 * 18; it += 128) {
            int r = it / 18, dq = (it % 18) * 4;
            size_t gi = (size_t)(k0 + r) * PROJ + hoff + dq;
            float4 kv = *(const float4*)(K + gi);
            float4 vv = *(const float4*)(V + gi);
            float kvv[4] = {kv.x, kv.y, kv.z, kv.w};
            float vvv[4] = {vv.x, vv.y, vv.z, vv.w};
            uint4 hk, lk, hv, lv;
            unsigned *hkp = &hk.x, *lkp = &lk.x, *hvp = &hv.x, *lvp = &lv.x;
            #pragma unroll
            for (int j = 0; j < 4; j++) {
                unsigned a = f2tf(kvv[j]); hkp[j] = a; lkp[j] = f2tf(kvv[j] - uif(a));
                unsigned b = f2tf(vvv[j]); hvp[j] = b; lvp[j] = f2tf(vvv[j] - uif(b));
            }
            *(uint4*)&Ksh[r * KST + dq] = hk;
            *(uint4*)&Ksl[r * KST + dq] = lk;
            *(uint4*)&Vsh[r * VST + dq] = hv;
            *(uint4*)&Vsl[r * VST + dq] = lv;
        }
        __syncthreads();

        // ---- S = Q @ K^T (tf32x3) ----
        float s[8][4];
        #pragma unroll
        for (int nt = 0; nt < 8; nt++)
            #pragma unroll
            for (int r = 0; r < 4; r++) s[nt][r] = 0.f;

        #pragma unroll
        for (int kt = 0; kt < 9; kt++) {
            int d0 = kt * 8;
            #pragma unroll
            for (int nt = 0; nt < 8; nt++) {
                int krow = nt * 8 + g;
                unsigned bh[2], bl[2];
                bh[0] = Ksh[krow * KST + d0 + tg];
                bh[1] = Ksh[krow * KST + d0 + tg + 4];
                bl[0] = Ksl[krow * KST + d0 + tg];
                bl[1] = Ksl[krow * KST + d0 + tg + 4];
                mma8(s[nt], qh[kt], bh);
                mma8(s[nt], qh[kt], bl);
                mma8(s[nt], ql[kt], bh);
            }
        }

        // ---- online softmax (rows arow, arow+8; cols spread over tg quad) ----
        float mt0 = s[0][0], mt1 = s[0][2];
        #pragma unroll
        for (int nt = 0; nt < 8; nt++) {
            mt0 = fmaxf(mt0, fmaxf(s[nt][0], s[nt][1]));
            mt1 = fmaxf(mt1, fmaxf(s[nt][2], s[nt][3]));
        }
        mt0 = fmaxf(mt0, __shfl_xor_sync(0xffffffffu, mt0, 1));
        mt0 = fmaxf(mt0, __shfl_xor_sync(0xffffffffu, mt0, 2));
        mt1 = fmaxf(mt1, __shfl_xor_sync(0xffffffffu, mt1, 1));
        mt1 = fmaxf(mt1, __shfl_xor_sync(0xffffffffu, mt1, 2));
        float nm0 = fmaxf(m0, mt0), nm1 = fmaxf(m1, mt1);
        float c0 = __expf(m0 - nm0), c1 = __expf(m1 - nm1);
        float ls0 = 0.f, ls1 = 0.f;
        #pragma unroll
        for (int nt = 0; nt < 8; nt++) {
            s[nt][0] = __expf(s[nt][0] - nm0); ls0 += s[nt][0];
            s[nt][1] = __expf(s[nt][1] - nm0); ls0 += s[nt][1];
            s[nt][2] = __expf(s[nt][2] - nm1); ls1 += s[nt][2];
            s[nt][3] = __expf(s[nt][3] - nm1); ls1 += s[nt][3];
        }
        ls0 += __shfl_xor_sync(0xffffffffu, ls0, 1);
        ls0 += __shfl_xor_sync(0xffffffffu, ls0, 2);
        ls1 += __shfl_xor_sync(0xffffffffu, ls1, 1);
        ls1 += __shfl_xor_sync(0xffffffffu, ls1, 2);
        l0 = l0 * c0 + ls0; m0 = nm0;
        l1 = l1 * c1 + ls1; m1 = nm1;
        #pragma unroll
        for (int nt = 0; nt < 9; nt++) {
            o[nt][0] *= c0; o[nt][1] *= c0;
            o[nt][2] *= c1; o[nt][3] *= c1;
        }

        // ---- publish P (hi/lo) to warp-private smem rows ----
        __syncwarp();   // prior-iter PV fragment reads done across the warp
        #pragma unroll
        for (int nt = 0; nt < 8; nt++) {
            int col = nt * 8 + 2 * tg;
            unsigned h0 = f2tf(s[nt][0]), h1 = f2tf(s[nt][1]);
            unsigned h2 = f2tf(s[nt][2]), h3 = f2tf(s[nt][3]);
            uint2 hv0 = make_uint2(h0, h1);
            uint2 hv1 = make_uint2(h2, h3);
            uint2 lv0 = make_uint2(f2tf(s[nt][0] - uif(h0)), f2tf(s[nt][1] - uif(h1)));
            uint2 lv1 = make_uint2(f2tf(s[nt][2] - uif(h2)), f2tf(s[nt][3] - uif(h3)));
            *(uint2*)&Psh[(arow)     * PST + col] = hv0;
            *(uint2*)&Psh[(arow + 8) * PST + col] = hv1;
            *(uint2*)&Psl[(arow)     * PST + col] = lv0;
            *(uint2*)&Psl[(arow + 8) * PST + col] = lv1;
        }
        __syncwarp();

        // ---- O += P @ V (tf32x3) ----
        #pragma unroll
        for (int kt = 0; kt < 8; kt++) {
            int kc = kt * 8;
            unsigned ah[4], al[4];
            ah[0] = Psh[(arow)     * PST + kc + tg];
            ah[1] = Psh[(arow + 8) * PST + kc + tg];
            ah[2] = Psh[(arow)     * PST + kc + tg + 4];
            ah[3] = Psh[(arow + 8) * PST + kc + tg + 4];
            al[0] = Psl[(arow)     * PST + kc + tg];
            al[1] = Psl[(arow + 8) * PST + kc + tg];
            al[2] = Psl[(arow)     * PST + kc + tg + 4];
            al[3] = Psl[(arow + 8) * PST + kc + tg + 4];
            #pragma unroll
            for (int nt = 0; nt < 9; nt++) {
                int nc = nt * 8 + g;
                unsigned bh[2], bl[2];
                bh[0] = Vsh[(kc + tg)     * VST + nc];
                bh[1] = Vsh[(kc + tg + 4) * VST + nc];
                bl[0] = Vsl[(kc + tg)     * VST + nc];
                bl[1] = Vsl[(kc + tg + 4) * VST + nc];
                mma8(o[nt], ah, bh);
                mma8(o[nt], ah, bl);
                mma8(o[nt], al, bh);
            }
        }
    }

    // ---- epilogue ----
    float inv0 = 1.f / l0, inv1 = 1.f / l1;
    #pragma unroll
    for (int nt = 0; nt < 9; nt++) {
        int c = hoff + nt * 8 + 2 * tg;
        int r = q0 + arow;
        float2 v0 = make_float2(o[nt][0] * inv0, o[nt][1] * inv0);
        float2 v1 = make_float2(o[nt][2] * inv1, o[nt][3] * inv1);
        *(float2*)(O + (size_t)r * PROJ + c)       = v0;
        *(float2*)(O + (size_t)(r + 8) * PROJ + c) = v1;
    }
}

// ---------------------------------------------------------------------------
extern "C" void kernel_launch(void* const* d_in, const int* in_sizes, int n_in,
                              void* d_out, int out_size)
{
    const float* hidden = (const float*)d_in[0];
    const float* cosp   = (const float*)d_in[1];
    const float* sinp   = (const float*)d_in[2];
    const float* Wq     = (const float*)d_in[3];
    const float* Wk     = (const float*)d_in[4];
    const float* Wv     = (const float*)d_in[5];
    const float* Wo     = (const float*)d_in[6];
    const float* qsc    = (const float*)d_in[7];
    const float* ksc    = (const float*)d_in[8];
    float* out = (float*)d_out;

    float *q, *k, *v, *o;
    cudaGetSymbolAddress((void**)&q, g_q);
    cudaGetSymbolAddress((void**)&k, g_k);
    cudaGetSymbolAddress((void**)&v, g_v);
    cudaGetSymbolAddress((void**)&o, g_o);

    dim3 gg(PROJ / 128, N_TOK / 128);
    gemm_x3_kernel<<<gg, 256>>>(hidden, Wq, q, N_TOK, PROJ, HIDDEN);
    gemm_x3_kernel<<<gg, 256>>>(hidden, Wk, k, N_TOK, PROJ, HIDDEN);
    gemm_x3_kernel<<<gg, 256>>>(hidden, Wv, v, N_TOK, PROJ, HIDDEN);

    normrope_kernel<<<(N_TOK * NUM_HEADS) / 8, 256>>>(cosp, sinp, qsc, ksc);

    cudaFuncSetAttribute(attn_mma_kernel,
                         cudaFuncAttributeMaxDynamicSharedMemorySize,
                         ATTN_SMEM_BYTES);
    attn_mma_kernel<<<dim3(NUM_HEADS, N_TOK / 64), 128, ATTN_SMEM_BYTES>>>(q, k, v, o);

    gemm_x3_kernel<<<gg, 256>>>(o, Wo, out, N_TOK, HIDDEN, PROJ);
}

// round 4
// speedup vs baseline: 2.0892x; 1.0191x over previous
#include <cuda_runtime.h>
#include <math.h>

#define N_TOK     4096
#define HIDDEN    1152
#define NUM_HEADS 16
#define HEAD_DIM  72
#define PROJ      1152   // NUM_HEADS * HEAD_DIM

// Scratch (device globals: allocation-free per harness rules)
__device__ float g_q[(size_t)N_TOK * PROJ];
__device__ float g_k[(size_t)N_TOK * PROJ];
__device__ float g_v[(size_t)N_TOK * PROJ];
__device__ float g_o[(size_t)N_TOK * PROJ];

// ---------------------------------------------------------------------------
// tf32 helpers
// ---------------------------------------------------------------------------
__device__ __forceinline__ unsigned f2tf(float x) {
    unsigned u;
    asm("cvt.rna.tf32.f32 %0, %1;" : "=r"(u) : "f"(x));
    return u;
}
__device__ __forceinline__ float uif(unsigned u) { return __uint_as_float(u); }

// D += A*B  (m16n8k8 tf32, row.col)
__device__ __forceinline__ void mma8(float c[4], const unsigned a[4], const unsigned b[2]) {
    asm("mma.sync.aligned.m16n8k8.row.col.f32.tf32.tf32.f32 "
        "{%0,%1,%2,%3},{%4,%5,%6,%7},{%8,%9},{%0,%1,%2,%3};"
        : "+f"(c[0]), "+f"(c[1]), "+f"(c[2]), "+f"(c[3])
        : "r"(a[0]), "r"(a[1]), "r"(a[2]), "r"(a[3]), "r"(b[0]), "r"(b[1]));
}

// ---------------------------------------------------------------------------
// tf32x3 GEMM with 2-stage smem double buffering.
// C[M,N] = A[M,K] @ B[K,N], row-major. Block 128x128, BK=8, 8 warps (64x32 each).
// grid.z selects (B, C) pair for batched QKV.
// ---------------------------------------------------------------------------
__global__ void __launch_bounds__(256) gemm_x3_kernel(
    const float* __restrict__ A,
    const float* __restrict__ B0, float* __restrict__ C0,
    const float* __restrict__ B1, float* __restrict__ C1,
    const float* __restrict__ B2, float* __restrict__ C2,
    int M, int N, int K)
{
    __shared__ unsigned Ah[2][8][136], Al[2][8][136];   // [stage][k][m]
    __shared__ unsigned Bh[2][8][136], Bl[2][8][136];   // [stage][k][n]

    const float* B = (blockIdx.z == 0) ? B0 : (blockIdx.z == 1) ? B1 : B2;
    float*       C = (blockIdx.z == 0) ? C0 : (blockIdx.z == 1) ? C1 : C2;

    const int tid  = threadIdx.x;
    const int lane = tid & 31;
    const int wid  = tid >> 5;
    const int row0 = blockIdx.y * 128;
    const int col0 = blockIdx.x * 128;
    const int warpM = (wid & 1) * 64;
    const int warpN = (wid >> 1) * 32;
    const int g  = lane >> 2;
    const int tg = lane & 3;

    const int aRow = tid >> 1;          // 0..127
    const int aC   = (tid & 1) * 4;     // 0 or 4
    const int bRow = tid >> 5;          // 0..7
    const int bC   = (tid & 31) * 4;    // 0..124

    float acc[4][4][4];
    #pragma unroll
    for (int mt = 0; mt < 4; mt++)
        #pragma unroll
        for (int nt = 0; nt < 4; nt++)
            #pragma unroll
            for (int r = 0; r < 4; r++) acc[mt][nt][r] = 0.f;

    // prologue: load + store slab 0 into stage 0
    float4 a4 = *(const float4*)(A + (size_t)(row0 + aRow) * K + aC);
    float4 b4 = *(const float4*)(B + (size_t)bRow * N + col0 + bC);
    {
        float av[4] = {a4.x, a4.y, a4.z, a4.w};
        #pragma unroll
        for (int j = 0; j < 4; j++) {
            unsigned hh = f2tf(av[j]);
            Ah[0][aC + j][aRow] = hh;
            Al[0][aC + j][aRow] = f2tf(av[j] - uif(hh));
        }
        float bv[4] = {b4.x, b4.y, b4.z, b4.w};
        uint4 hh, ll;
        unsigned* hp = &hh.x; unsigned* lp = &ll.x;
        #pragma unroll
        for (int j = 0; j < 4; j++) {
            unsigned hv = f2tf(bv[j]);
            hp[j] = hv;
            lp[j] = f2tf(bv[j] - uif(hv));
        }
        *(uint4*)&Bh[0][bRow][bC] = hh;
        *(uint4*)&Bl[0][bRow][bC] = ll;
    }
    __syncthreads();

    int cur = 0;
    for (int k0 = 0; k0 < K; k0 += 8) {
        const bool more = (k0 + 8 < K);
        if (more) {
            a4 = *(const float4*)(A + (size_t)(row0 + aRow) * K + (k0 + 8) + aC);
            b4 = *(const float4*)(B + (size_t)(k0 + 8 + bRow) * N + col0 + bC);
        }

        // fragments from current stage
        unsigned ah[4][4], al[4][4], bh[4][2], bl[4][2];
        #pragma unroll
        for (int mt = 0; mt < 4; mt++) {
            int m = warpM + mt * 16 + g;
            ah[mt][0] = Ah[cur][tg][m];     ah[mt][1] = Ah[cur][tg][m + 8];
            ah[mt][2] = Ah[cur][tg + 4][m]; ah[mt][3] = Ah[cur][tg + 4][m + 8];
            al[mt][0] = Al[cur][tg][m];     al[mt][1] = Al[cur][tg][m + 8];
            al[mt][2] = Al[cur][tg + 4][m]; al[mt][3] = Al[cur][tg + 4][m + 8];
        }
        #pragma unroll
        for (int nt = 0; nt < 4; nt++) {
            int n = warpN + nt * 8 + g;
            bh[nt][0] = Bh[cur][tg][n]; bh[nt][1] = Bh[cur][tg + 4][n];
            bl[nt][0] = Bl[cur][tg][n]; bl[nt][1] = Bl[cur][tg + 4][n];
        }
        #pragma unroll
        for (int mt = 0; mt < 4; mt++)
            #pragma unroll
            for (int nt = 0; nt < 4; nt++) {
                mma8(acc[mt][nt], ah[mt], bh[nt]);   // hi*hi
                mma8(acc[mt][nt], ah[mt], bl[nt]);   // hi*lo
                mma8(acc[mt][nt], al[mt], bh[nt]);   // lo*hi
            }

        if (more) {
            int nxt = cur ^ 1;
            float av[4] = {a4.x, a4.y, a4.z, a4.w};
            #pragma unroll
            for (int j = 0; j < 4; j++) {
                unsigned hh = f2tf(av[j]);
                Ah[nxt][aC + j][aRow] = hh;
                Al[nxt][aC + j][aRow] = f2tf(av[j] - uif(hh));
            }
            float bv[4] = {b4.x, b4.y, b4.z, b4.w};
            uint4 hh, ll;
            unsigned* hp = &hh.x; unsigned* lp = &ll.x;
            #pragma unroll
            for (int j = 0; j < 4; j++) {
                unsigned hv = f2tf(bv[j]);
                hp[j] = hv;
                lp[j] = f2tf(bv[j] - uif(hv));
            }
            *(uint4*)&Bh[nxt][bRow][bC] = hh;
            *(uint4*)&Bl[nxt][bRow][bC] = ll;
            __syncthreads();
            cur = nxt;
        }
    }

    #pragma unroll
    for (int mt = 0; mt < 4; mt++)
        #pragma unroll
        for (int nt = 0; nt < 4; nt++) {
            int r = row0 + warpM + mt * 16 + g;
            int c = col0 + warpN + nt * 8 + 2 * tg;
            float2 v0 = make_float2(acc[mt][nt][0], acc[mt][nt][1]);
            float2 v1 = make_float2(acc[mt][nt][2], acc[mt][nt][3]);
            *(float2*)(C + (size_t)r * N + c)       = v0;
            *(float2*)(C + (size_t)(r + 8) * N + c) = v1;
        }
}

// ---------------------------------------------------------------------------
// Fused RMSNorm + 2D RoPE (one warp per (token, head))
// ---------------------------------------------------------------------------
__device__ __forceinline__ float warp_sum(float v) {
    #pragma unroll
    for (int o = 16; o > 0; o >>= 1) v += __shfl_xor_sync(0xffffffffu, v, o);
    return v;
}

__global__ void __launch_bounds__(256) normrope_kernel(
    const float* __restrict__ cosp, const float* __restrict__ sinp,
    const float* __restrict__ qscale, const float* __restrict__ kscale)
{
    __shared__ float buf[8][72];
    const int warp = threadIdx.x >> 5;
    const int lane = threadIdx.x & 31;
    const int gw = blockIdx.x * 8 + warp;
    const int n = gw >> 4;
    const int h = gw & 15;
    const size_t off = (size_t)n * PROJ + h * HEAD_DIM;
    const float* crow = cosp + (size_t)n * HEAD_DIM;
    const float* srow = sinp + (size_t)n * HEAD_DIM;

    float* bufs[3] = { g_q + off, g_k + off, g_v + off };

    for (int w = 0; w < 3; w++) {
        float* p = bufs[w];
        float ss = 0.f;
        for (int d = lane; d < HEAD_DIM; d += 32) {
            float x = p[d];
            buf[warp][d] = x;
            ss += x * x;
        }
        ss = warp_sum(ss);
        float r = rsqrtf(ss * (1.f / HEAD_DIM) + 1e-6f);
        __syncwarp();
        for (int d = lane; d < HEAD_DIM; d += 32) {
            float y = buf[warp][d] * r;
            if (w == 0)      y *= qscale[d];
            else if (w == 1) y *= kscale[d];
            buf[warp][d] = y;
        }
        __syncwarp();
        if (w < 2) {
            for (int d = lane; d < HEAD_DIM; d += 32) {
                int j = (d < 36) ? d : d - 36;
                float rot = (j < 18) ? -buf[warp][d + 18] : buf[warp][d - 18];
                p[d] = buf[warp][d] * crow[d] + rot * srow[d];
            }
        } else {
            for (int d = lane; d < HEAD_DIM; d += 32) p[d] = buf[warp][d];
        }
        __syncwarp();
    }
}

// ---------------------------------------------------------------------------
// Flash attention with tf32x3 mma. 128-query tiles, 8 warps (256 threads);
// warp w owns S/O rows 16w..16w+15. 64-key tiles.
// K staged [key][d] stride 76, V [key][d] stride 72, P [row][key] stride 76.
// ---------------------------------------------------------------------------
#define TQ  128
#define KST 76
#define VST 72
#define PST 76
#define SM_KS  (64 * KST)
#define SM_VS  (64 * VST)
#define SM_PS  (TQ * PST)
#define ATTN_SMEM_BYTES ((2 * SM_KS + 2 * SM_VS + 2 * SM_PS) * 4)

__global__ void __launch_bounds__(256) attn_mma_kernel(
    const float* __restrict__ Q, const float* __restrict__ K,
    const float* __restrict__ V, float* __restrict__ O)
{
    extern __shared__ unsigned sm[];
    unsigned* Ksh = sm;
    unsigned* Ksl = Ksh + SM_KS;
    unsigned* Vsh = Ksl + SM_KS;
    unsigned* Vsl = Vsh + SM_VS;
    unsigned* Psh = Vsl + SM_VS;
    unsigned* Psl = Psh + SM_PS;
    float* Qs = (float*)Psh;   // staging alias (consumed before P writes)

    const int h    = blockIdx.x;
    const int q0   = blockIdx.y * TQ;
    const int tid  = threadIdx.x;
    const int lane = tid & 31;
    const int w    = tid >> 5;
    const int g    = lane >> 2;
    const int tg   = lane & 3;
    const int hoff = h * HEAD_DIM;
    const int arow = w * 16 + g;     // first S-row this thread touches

    // ---- stage Q tile, extract A fragments (hi/lo) ----
    for (int it = tid; it < TQ * 18; it += 256) {
        int r = it / 18, dq = (it % 18) * 4;
        float4 v = *(const float4*)(Q + (size_t)(q0 + r) * PROJ + hoff + dq);
        Qs[r * PST + dq + 0] = v.x;
        Qs[r * PST + dq + 1] = v.y;
        Qs[r * PST + dq + 2] = v.z;
        Qs[r * PST + dq + 3] = v.w;
    }
    __syncthreads();

    unsigned qh[9][4], ql[9][4];
    #pragma unroll
    for (int kt = 0; kt < 9; kt++) {
        float x0 = Qs[(arow)     * PST + kt * 8 + tg];
        float x1 = Qs[(arow + 8) * PST + kt * 8 + tg];
        float x2 = Qs[(arow)     * PST + kt * 8 + tg + 4];
        float x3 = Qs[(arow + 8) * PST + kt * 8 + tg + 4];
        qh[kt][0] = f2tf(x0); ql[kt][0] = f2tf(x0 - uif(qh[kt][0]));
        qh[kt][1] = f2tf(x1); ql[kt][1] = f2tf(x1 - uif(qh[kt][1]));
        qh[kt][2] = f2tf(x2); ql[kt][2] = f2tf(x2 - uif(qh[kt][2]));
        qh[kt][3] = f2tf(x3); ql[kt][3] = f2tf(x3 - uif(qh[kt][3]));
    }
    __syncthreads();   // all Q reads done before any P writes

    float m0 = -1e30f, m1 = -1e30f, l0 = 0.f, l1 = 0.f;
    float o[9][4];
    #pragma unroll
    for (int nt = 0; nt < 9; nt++)
        #pragma unroll
        for (int r = 0; r < 4; r++) o[nt][r] = 0.f;

    for (int k0 = 0; k0 < N_TOK; k0 += 64) {
        __syncthreads();   // previous tile fully consumed
        // ---- load K,V tile, split hi/lo ----
        for (int it = tid; it < 64 * 18; it += 256) {
            int r = it / 18, dq = (it % 18) * 4;
            size_t gi = (size_t)(k0 + r) * PROJ + hoff + dq;
            float4 kv = *(const float4*)(K + gi);
            float4 vv = *(const float4*)(V + gi);
            float kvv[4] = {kv.x, kv.y, kv.z, kv.w};
            float vvv[4] = {vv.x, vv.y, vv.z, vv.w};
            uint4 hk, lk, hv, lv;
            unsigned *hkp = &hk.x, *lkp = &lk.x, *hvp = &hv.x, *lvp = &lv.x;
            #pragma unroll
            for (int j = 0; j < 4; j++) {
                unsigned a = f2tf(kvv[j]); hkp[j] = a; lkp[j] = f2tf(kvv[j] - uif(a));
                unsigned b = f2tf(vvv[j]); hvp[j] = b; lvp[j] = f2tf(vvv[j] - uif(b));
            }
            *(uint4*)&Ksh[r * KST + dq] = hk;
            *(uint4*)&Ksl[r * KST + dq] = lk;
            *(uint4*)&Vsh[r * VST + dq] = hv;
            *(uint4*)&Vsl[r * VST + dq] = lv;
        }
        __syncthreads();

        // ---- S = Q @ K^T (tf32x3) ----
        float s[8][4];
        #pragma unroll
        for (int nt = 0; nt < 8; nt++)
            #pragma unroll
            for (int r = 0; r < 4; r++) s[nt][r] = 0.f;

        #pragma unroll
        for (int kt = 0; kt < 9; kt++) {
            int d0 = kt * 8;
            #pragma unroll
            for (int nt = 0; nt < 8; nt++) {
                int krow = nt * 8 + g;
                unsigned bh[2], bl[2];
                bh[0] = Ksh[krow * KST + d0 + tg];
                bh[1] = Ksh[krow * KST + d0 + tg + 4];
                bl[0] = Ksl[krow * KST + d0 + tg];
                bl[1] = Ksl[krow * KST + d0 + tg + 4];
                mma8(s[nt], qh[kt], bh);
                mma8(s[nt], qh[kt], bl);
                mma8(s[nt], ql[kt], bh);
            }
        }

        // ---- online softmax (rows arow, arow+8) ----
        float mt0 = s[0][0], mt1 = s[0][2];
        #pragma unroll
        for (int nt = 0; nt < 8; nt++) {
            mt0 = fmaxf(mt0, fmaxf(s[nt][0], s[nt][1]));
            mt1 = fmaxf(mt1, fmaxf(s[nt][2], s[nt][3]));
        }
        mt0 = fmaxf(mt0, __shfl_xor_sync(0xffffffffu, mt0, 1));
        mt0 = fmaxf(mt0, __shfl_xor_sync(0xffffffffu, mt0, 2));
        mt1 = fmaxf(mt1, __shfl_xor_sync(0xffffffffu, mt1, 1));
        mt1 = fmaxf(mt1, __shfl_xor_sync(0xffffffffu, mt1, 2));
        float nm0 = fmaxf(m0, mt0), nm1 = fmaxf(m1, mt1);
        float c0 = __expf(m0 - nm0), c1 = __expf(m1 - nm1);
        float ls0 = 0.f, ls1 = 0.f;
        #pragma unroll
        for (int nt = 0; nt < 8; nt++) {
            s[nt][0] = __expf(s[nt][0] - nm0); ls0 += s[nt][0];
            s[nt][1] = __expf(s[nt][1] - nm0); ls0 += s[nt][1];
            s[nt][2] = __expf(s[nt][2] - nm1); ls1 += s[nt][2];
            s[nt][3] = __expf(s[nt][3] - nm1); ls1 += s[nt][3];
        }
        ls0 += __shfl_xor_sync(0xffffffffu, ls0, 1);
        ls0 += __shfl_xor_sync(0xffffffffu, ls0, 2);
        ls1 += __shfl_xor_sync(0xffffffffu, ls1, 1);
        ls1 += __shfl_xor_sync(0xffffffffu, ls1, 2);
        l0 = l0 * c0 + ls0; m0 = nm0;
        l1 = l1 * c1 + ls1; m1 = nm1;
        #pragma unroll
        for (int nt = 0; nt < 9; nt++) {
            o[nt][0] *= c0; o[nt][1] *= c0;
            o[nt][2] *= c1; o[nt][3] *= c1;
        }

        // ---- publish P (hi/lo) to warp-private smem rows ----
        __syncwarp();
        #pragma unroll
        for (int nt = 0; nt < 8; nt++) {
            int col = nt * 8 + 2 * tg;
            unsigned h0 = f2tf(s[nt][0]), h1 = f2tf(s[nt][1]);
            unsigned h2 = f2tf(s[nt][2]), h3 = f2tf(s[nt][3]);
            uint2 hv0 = make_uint2(h0, h1);
            uint2 hv1 = make_uint2(h2, h3);
            uint2 lv0 = make_uint2(f2tf(s[nt][0] - uif(h0)), f2tf(s[nt][1] - uif(h1)));
            uint2 lv1 = make_uint2(f2tf(s[nt][2] - uif(h2)), f2tf(s[nt][3] - uif(h3)));
            *(uint2*)&Psh[(arow)     * PST + col] = hv0;
            *(uint2*)&Psh[(arow + 8) * PST + col] = hv1;
            *(uint2*)&Psl[(arow)     * PST + col] = lv0;
            *(uint2*)&Psl[(arow + 8) * PST + col] = lv1;
        }
        __syncwarp();

        // ---- O += P @ V (tf32x3) ----
        #pragma unroll
        for (int kt = 0; kt < 8; kt++) {
            int kc = kt * 8;
            unsigned ah[4], al[4];
            ah[0] = Psh[(arow)     * PST + kc + tg];
            ah[1] = Psh[(arow + 8) * PST + kc + tg];
            ah[2] = Psh[(arow)     * PST + kc + tg + 4];
            ah[3] = Psh[(arow + 8) * PST + kc + tg + 4];
            al[0] = Psl[(arow)     * PST + kc + tg];
            al[1] = Psl[(arow + 8) * PST + kc + tg];
            al[2] = Psl[(arow)     * PST + kc + tg + 4];
            al[3] = Psl[(arow + 8) * PST + kc + tg + 4];
            #pragma unroll
            for (int nt = 0; nt < 9; nt++) {
                int nc = nt * 8 + g;
                unsigned bh[2], bl[2];
                bh[0] = Vsh[(kc + tg)     * VST + nc];
                bh[1] = Vsh[(kc + tg + 4) * VST + nc];
                bl[0] = Vsl[(kc + tg)     * VST + nc];
                bl[1] = Vsl[(kc + tg + 4) * VST + nc];
                mma8(o[nt], ah, bh);
                mma8(o[nt], ah, bl);
                mma8(o[nt], al, bh);
            }
        }
    }

    // ---- epilogue ----
    float inv0 = 1.f / l0, inv1 = 1.f / l1;
    #pragma unroll
    for (int nt = 0; nt < 9; nt++) {
        int c = hoff + nt * 8 + 2 * tg;
        int r = q0 + arow;
        float2 v0 = make_float2(o[nt][0] * inv0, o[nt][1] * inv0);
        float2 v1 = make_float2(o[nt][2] * inv1, o[nt][3] * inv1);
        *(float2*)(O + (size_t)r * PROJ + c)       = v0;
        *(float2*)(O + (size_t)(r + 8) * PROJ + c) = v1;
    }
}

// ---------------------------------------------------------------------------
extern "C" void kernel_launch(void* const* d_in, const int* in_sizes, int n_in,
                              void* d_out, int out_size)
{
    const float* hidden = (const float*)d_in[0];
    const float* cosp   = (const float*)d_in[1];
    const float* sinp   = (const float*)d_in[2];
    const float* Wq     = (const float*)d_in[3];
    const float* Wk     = (const float*)d_in[4];
    const float* Wv     = (const float*)d_in[5];
    const float* Wo     = (const float*)d_in[6];
    const float* qsc    = (const float*)d_in[7];
    const float* ksc    = (const float*)d_in[8];
    float* out = (float*)d_out;

    float *q, *k, *v, *o;
    cudaGetSymbolAddress((void**)&q, g_q);
    cudaGetSymbolAddress((void**)&k, g_k);
    cudaGetSymbolAddress((void**)&v, g_v);
    cudaGetSymbolAddress((void**)&o, g_o);

    // fused QKV: grid.z selects weight/output
    dim3 gq(PROJ / 128, N_TOK / 128, 3);
    gemm_x3_kernel<<<gq, 256>>>(hidden, Wq, q, Wk, k, Wv, v, N_TOK, PROJ, HIDDEN);

    normrope_kernel<<<(N_TOK * NUM_HEADS) / 8, 256>>>(cosp, sinp, qsc, ksc);

    cudaFuncSetAttribute(attn_mma_kernel,
                         cudaFuncAttributeMaxDynamicSharedMemorySize,
                         ATTN_SMEM_BYTES);
    attn_mma_kernel<<<dim3(NUM_HEADS, N_TOK / TQ), 256, ATTN_SMEM_BYTES>>>(q, k, v, o);

    dim3 go(HIDDEN / 128, N_TOK / 128, 1);
    gemm_x3_kernel<<<go, 256>>>(o, Wo, out, Wo, out, Wo, out, N_TOK, HIDDEN, PROJ);
}

// round 5
// speedup vs baseline: 2.2747x; 1.0888x over previous
#include <cuda_runtime.h>
#include <cuda_fp16.h>
#include <math.h>

#define N_TOK     4096
#define HIDDEN    1152
#define NUM_HEADS 16
#define HEAD_DIM  72
#define PROJ      1152   // NUM_HEADS * HEAD_DIM

// Scratch (device globals: allocation-free per harness rules)
__device__ float g_q[(size_t)N_TOK * PROJ];
__device__ float g_k[(size_t)N_TOK * PROJ];
__device__ float g_v[(size_t)N_TOK * PROJ];
__device__ float g_o[(size_t)N_TOK * PROJ];

// ---------------------------------------------------------------------------
// tf32 helpers (GEMM path, unchanged)
// ---------------------------------------------------------------------------
__device__ __forceinline__ unsigned f2tf(float x) {
    unsigned u;
    asm("cvt.rna.tf32.f32 %0, %1;" : "=r"(u) : "f"(x));
    return u;
}
__device__ __forceinline__ float uif(unsigned u) { return __uint_as_float(u); }

__device__ __forceinline__ void mma8(float c[4], const unsigned a[4], const unsigned b[2]) {
    asm("mma.sync.aligned.m16n8k8.row.col.f32.tf32.tf32.f32 "
        "{%0,%1,%2,%3},{%4,%5,%6,%7},{%8,%9},{%0,%1,%2,%3};"
        : "+f"(c[0]), "+f"(c[1]), "+f"(c[2]), "+f"(c[3])
        : "r"(a[0]), "r"(a[1]), "r"(a[2]), "r"(a[3]), "r"(b[0]), "r"(b[1]));
}

// ---------------------------------------------------------------------------
// fp16 helpers (attention path)
// ---------------------------------------------------------------------------
// pack two f32 into half2: low = lo_elem, high = hi_elem
__device__ __forceinline__ unsigned packh2(float lo, float hi) {
    unsigned r;
    asm("cvt.rn.f16x2.f32 %0, %1, %2;" : "=r"(r) : "f"(hi), "f"(lo));
    return r;
}
__device__ __forceinline__ float2 h22f(unsigned u) {
    __half2 h = *reinterpret_cast<__half2*>(&u);
    return __half22float2(h);
}
// split pair (a,b) into fp16 hi half2 + fp16 lo-residue half2
__device__ __forceinline__ void split2(float a, float b, unsigned &h, unsigned &l) {
    h = packh2(a, b);
    float2 f = h22f(h);
    l = packh2(a - f.x, b - f.y);
}

// D += A*B  (m16n8k16 fp16 -> f32)
__device__ __forceinline__ void mma16h(float c[4], const unsigned a[4],
                                       unsigned b0, unsigned b1) {
    asm("mma.sync.aligned.m16n8k16.row.col.f32.f16.f16.f32 "
        "{%0,%1,%2,%3},{%4,%5,%6,%7},{%8,%9},{%0,%1,%2,%3};"
        : "+f"(c[0]), "+f"(c[1]), "+f"(c[2]), "+f"(c[3])
        : "r"(a[0]), "r"(a[1]), "r"(a[2]), "r"(a[3]), "r"(b0), "r"(b1));
}
// D += A*B  (m16n8k8 fp16 -> f32)
__device__ __forceinline__ void mma8h(float c[4], const unsigned a[2], unsigned b0) {
    asm("mma.sync.aligned.m16n8k8.row.col.f32.f16.f16.f32 "
        "{%0,%1,%2,%3},{%4,%5},{%6},{%0,%1,%2,%3};"
        : "+f"(c[0]), "+f"(c[1]), "+f"(c[2]), "+f"(c[3])
        : "r"(a[0]), "r"(a[1]), "r"(b0));
}

// ---------------------------------------------------------------------------
// tf32x3 GEMM with 2-stage smem double buffering (unchanged from R4).
// ---------------------------------------------------------------------------
__global__ void __launch_bounds__(256) gemm_x3_kernel(
    const float* __restrict__ A,
    const float* __restrict__ B0, float* __restrict__ C0,
    const float* __restrict__ B1, float* __restrict__ C1,
    const float* __restrict__ B2, float* __restrict__ C2,
    int M, int N, int K)
{
    __shared__ unsigned Ah[2][8][136], Al[2][8][136];
    __shared__ unsigned Bh[2][8][136], Bl[2][8][136];

    const float* B = (blockIdx.z == 0) ? B0 : (blockIdx.z == 1) ? B1 : B2;
    float*       C = (blockIdx.z == 0) ? C0 : (blockIdx.z == 1) ? C1 : C2;

    const int tid  = threadIdx.x;
    const int lane = tid & 31;
    const int wid  = tid >> 5;
    const int row0 = blockIdx.y * 128;
    const int col0 = blockIdx.x * 128;
    const int warpM = (wid & 1) * 64;
    const int warpN = (wid >> 1) * 32;
    const int g  = lane >> 2;
    const int tg = lane & 3;

    const int aRow = tid >> 1;
    const int aC   = (tid & 1) * 4;
    const int bRow = tid >> 5;
    const int bC   = (tid & 31) * 4;

    float acc[4][4][4];
    #pragma unroll
    for (int mt = 0; mt < 4; mt++)
        #pragma unroll
        for (int nt = 0; nt < 4; nt++)
            #pragma unroll
            for (int r = 0; r < 4; r++) acc[mt][nt][r] = 0.f;

    float4 a4 = *(const float4*)(A + (size_t)(row0 + aRow) * K + aC);
    float4 b4 = *(const float4*)(B + (size_t)bRow * N + col0 + bC);
    {
        float av[4] = {a4.x, a4.y, a4.z, a4.w};
        #pragma unroll
        for (int j = 0; j < 4; j++) {
            unsigned hh = f2tf(av[j]);
            Ah[0][aC + j][aRow] = hh;
            Al[0][aC + j][aRow] = f2tf(av[j] - uif(hh));
        }
        float bv[4] = {b4.x, b4.y, b4.z, b4.w};
        uint4 hh, ll;
        unsigned* hp = &hh.x; unsigned* lp = &ll.x;
        #pragma unroll
        for (int j = 0; j < 4; j++) {
            unsigned hv = f2tf(bv[j]);
            hp[j] = hv;
            lp[j] = f2tf(bv[j] - uif(hv));
        }
        *(uint4*)&Bh[0][bRow][bC] = hh;
        *(uint4*)&Bl[0][bRow][bC] = ll;
    }
    __syncthreads();

    int cur = 0;
    for (int k0 = 0; k0 < K; k0 += 8) {
        const bool more = (k0 + 8 < K);
        if (more) {
            a4 = *(const float4*)(A + (size_t)(row0 + aRow) * K + (k0 + 8) + aC);
            b4 = *(const float4*)(B + (size_t)(k0 + 8 + bRow) * N + col0 + bC);
        }

        unsigned ah[4][4], al[4][4], bh[4][2], bl[4][2];
        #pragma unroll
        for (int mt = 0; mt < 4; mt++) {
            int m = warpM + mt * 16 + g;
            ah[mt][0] = Ah[cur][tg][m];     ah[mt][1] = Ah[cur][tg][m + 8];
            ah[mt][2] = Ah[cur][tg + 4][m]; ah[mt][3] = Ah[cur][tg + 4][m + 8];
            al[mt][0] = Al[cur][tg][m];     al[mt][1] = Al[cur][tg][m + 8];
            al[mt][2] = Al[cur][tg + 4][m]; al[mt][3] = Al[cur][tg + 4][m + 8];
        }
        #pragma unroll
        for (int nt = 0; nt < 4; nt++) {
            int n = warpN + nt * 8 + g;
            bh[nt][0] = Bh[cur][tg][n]; bh[nt][1] = Bh[cur][tg + 4][n];
            bl[nt][0] = Bl[cur][tg][n]; bl[nt][1] = Bl[cur][tg + 4][n];
        }
        #pragma unroll
        for (int mt = 0; mt < 4; mt++)
            #pragma unroll
            for (int nt = 0; nt < 4; nt++) {
                mma8(acc[mt][nt], ah[mt], bh[nt]);
                mma8(acc[mt][nt], ah[mt], bl[nt]);
                mma8(acc[mt][nt], al[mt], bh[nt]);
            }

        if (more) {
            int nxt = cur ^ 1;
            float av[4] = {a4.x, a4.y, a4.z, a4.w};
            #pragma unroll
            for (int j = 0; j < 4; j++) {
                unsigned hh = f2tf(av[j]);
                Ah[nxt][aC + j][aRow] = hh;
                Al[nxt][aC + j][aRow] = f2tf(av[j] - uif(hh));
            }
            float bv[4] = {b4.x, b4.y, b4.z, b4.w};
            uint4 hh, ll;
            unsigned* hp = &hh.x; unsigned* lp = &ll.x;
            #pragma unroll
            for (int j = 0; j < 4; j++) {
                unsigned hv = f2tf(bv[j]);
                hp[j] = hv;
                lp[j] = f2tf(bv[j] - uif(hv));
            }
            *(uint4*)&Bh[nxt][bRow][bC] = hh;
            *(uint4*)&Bl[nxt][bRow][bC] = ll;
            __syncthreads();
            cur = nxt;
        }
    }

    #pragma unroll
    for (int mt = 0; mt < 4; mt++)
        #pragma unroll
        for (int nt = 0; nt < 4; nt++) {
            int r = row0 + warpM + mt * 16 + g;
            int c = col0 + warpN + nt * 8 + 2 * tg;
            float2 v0 = make_float2(acc[mt][nt][0], acc[mt][nt][1]);
            float2 v1 = make_float2(acc[mt][nt][2], acc[mt][nt][3]);
            *(float2*)(C + (size_t)r * N + c)       = v0;
            *(float2*)(C + (size_t)(r + 8) * N + c) = v1;
        }
}

// ---------------------------------------------------------------------------
// Fused RMSNorm + 2D RoPE (unchanged)
// ---------------------------------------------------------------------------
__device__ __forceinline__ float warp_sum(float v) {
    #pragma unroll
    for (int o = 16; o > 0; o >>= 1) v += __shfl_xor_sync(0xffffffffu, v, o);
    return v;
}

__global__ void __launch_bounds__(256) normrope_kernel(
    const float* __restrict__ cosp, const float* __restrict__ sinp,
    const float* __restrict__ qscale, const float* __restrict__ kscale)
{
    __shared__ float buf[8][72];
    const int warp = threadIdx.x >> 5;
    const int lane = threadIdx.x & 31;
    const int gw = blockIdx.x * 8 + warp;
    const int n = gw >> 4;
    const int h = gw & 15;
    const size_t off = (size_t)n * PROJ + h * HEAD_DIM;
    const float* crow = cosp + (size_t)n * HEAD_DIM;
    const float* srow = sinp + (size_t)n * HEAD_DIM;

    float* bufs[3] = { g_q + off, g_k + off, g_v + off };

    for (int w = 0; w < 3; w++) {
        float* p = bufs[w];
        float ss = 0.f;
        for (int d = lane; d < HEAD_DIM; d += 32) {
            float x = p[d];
            buf[warp][d] = x;
            ss += x * x;
        }
        ss = warp_sum(ss);
        float r = rsqrtf(ss * (1.f / HEAD_DIM) + 1e-6f);
        __syncwarp();
        for (int d = lane; d < HEAD_DIM; d += 32) {
            float y = buf[warp][d] * r;
            if (w == 0)      y *= qscale[d];
            else if (w == 1) y *= kscale[d];
            buf[warp][d] = y;
        }
        __syncwarp();
        if (w < 2) {
            for (int d = lane; d < HEAD_DIM; d += 32) {
                int j = (d < 36) ? d : d - 36;
                float rot = (j < 18) ? -buf[warp][d + 18] : buf[warp][d - 18];
                p[d] = buf[warp][d] * crow[d] + rot * srow[d];
            }
        } else {
            for (int d = lane; d < HEAD_DIM; d += 32) p[d] = buf[warp][d];
        }
        __syncwarp();
    }
}

// ---------------------------------------------------------------------------
// Flash attention, fp16x3 (hi+lo error-compensated) m16n8k16 mma.
// Block = (head, 128-query tile), 8 warps; warp w owns S/O rows 16w..16w+15.
// Smem layout (u32 units):
//   Ksh [64 keys][36 half2]  hi   (d pairs along half2)        2304
//   Ksl [64][36]             lo                                2304
//   Vs  [64 keys][76 f32]    fp32 (converted per-use)          4864 f32
//   Ph  [128 rows][36 half2] P hi (key pairs along half2)      4608
//   Pl  [128][36]            P lo                              4608
// Qs (fp32, [128][72]) aliases Ph+Pl (consumed before first P write).
// ---------------------------------------------------------------------------
#define ATTN_SMEM_U32 (2304 + 2304 + 4864 + 4608 + 4608)
#define ATTN_SMEM_BYTES (ATTN_SMEM_U32 * 4)

__global__ void __launch_bounds__(256) attn_h3_kernel(
    const float* __restrict__ Q, const float* __restrict__ K,
    const float* __restrict__ V, float* __restrict__ O)
{
    extern __shared__ unsigned sm[];
    unsigned* Ksh = sm;
    unsigned* Ksl = sm + 2304;
    float*    Vs  = (float*)(sm + 4608);
    unsigned* Ph  = sm + 9472;
    unsigned* Pl  = sm + 14080;
    float*    Qs  = (float*)Ph;      // 128*72 f32 = 36864B = Ph+Pl region

    const int h    = blockIdx.x;
    const int q0   = blockIdx.y * 128;
    const int tid  = threadIdx.x;
    const int lane = tid & 31;
    const int w    = tid >> 5;
    const int g    = lane >> 2;
    const int tg   = lane & 3;
    const int hoff = h * HEAD_DIM;
    const int arow = w * 16 + g;

    // ---- stage Q (fp32) ----
    for (int it = tid; it < 128 * 18; it += 256) {
        int r = it / 18, c = it - r * 18;
        float4 v = *(const float4*)(Q + (size_t)(q0 + r) * PROJ + hoff + 4 * c);
        *(float4*)&Qs[r * 72 + 4 * c] = v;
    }
    __syncthreads();

    // ---- extract Q fragments (hi/lo fp16), 4 k16 steps + 1 k8 tail ----
    unsigned qh[4][4], ql[4][4], q8h[2], q8l[2];
    #pragma unroll
    for (int ks = 0; ks < 4; ks++) {
        float2 x0 = *(float2*)&Qs[(arow)     * 72 + 16 * ks + 2 * tg];
        float2 x1 = *(float2*)&Qs[(arow + 8) * 72 + 16 * ks + 2 * tg];
        float2 x2 = *(float2*)&Qs[(arow)     * 72 + 16 * ks + 2 * tg + 8];
        float2 x3 = *(float2*)&Qs[(arow + 8) * 72 + 16 * ks + 2 * tg + 8];
        split2(x0.x, x0.y, qh[ks][0], ql[ks][0]);
        split2(x1.x, x1.y, qh[ks][1], ql[ks][1]);
        split2(x2.x, x2.y, qh[ks][2], ql[ks][2]);
        split2(x3.x, x3.y, qh[ks][3], ql[ks][3]);
    }
    {
        float2 x0 = *(float2*)&Qs[(arow)     * 72 + 64 + 2 * tg];
        float2 x1 = *(float2*)&Qs[(arow + 8) * 72 + 64 + 2 * tg];
        split2(x0.x, x0.y, q8h[0], q8l[0]);
        split2(x1.x, x1.y, q8h[1], q8l[1]);
    }

    float m0 = -1e30f, m1 = -1e30f, l0 = 0.f, l1 = 0.f;
    float o[9][4];
    #pragma unroll
    for (int nt = 0; nt < 9; nt++)
        #pragma unroll
        for (int r = 0; r < 4; r++) o[nt][r] = 0.f;

    const int kb = g * 36 + tg;   // b-frag base within a K nt-group

    for (int k0 = 0; k0 < N_TOK; k0 += 64) {
        __syncthreads();   // previous tile consumed; Q extraction done (iter 0)
        // ---- load K (fp16 hi/lo split) ----
        for (int it = tid; it < 1152; it += 256) {
            int r = it / 18, c = it - r * 18;
            float4 kv = *(const float4*)(K + (size_t)(k0 + r) * PROJ + hoff + 4 * c);
            unsigned h01, l01, h23, l23;
            split2(kv.x, kv.y, h01, l01);
            split2(kv.z, kv.w, h23, l23);
            *(uint2*)&Ksh[r * 36 + 2 * c] = make_uint2(h01, h23);
            *(uint2*)&Ksl[r * 36 + 2 * c] = make_uint2(l01, l23);
        }
        // ---- load V (fp32) ----
        for (int it = tid; it < 1152; it += 256) {
            int r = it / 18, c = it - r * 18;
            *(float4*)&Vs[r * 76 + 4 * c] =
                *(const float4*)(V + (size_t)(k0 + r) * PROJ + hoff + 4 * c);
        }
        __syncthreads();

        // ---- S = Q @ K^T (fp16x3) ----
        float s[8][4];
        #pragma unroll
        for (int nt = 0; nt < 8; nt++)
            #pragma unroll
            for (int r = 0; r < 4; r++) s[nt][r] = 0.f;

        #pragma unroll
        for (int ks = 0; ks < 4; ks++) {
            #pragma unroll
            for (int nt = 0; nt < 8; nt++) {
                int base = nt * 288 + kb + 8 * ks;
                unsigned bh0 = Ksh[base],     bh1 = Ksh[base + 4];
                unsigned bl0 = Ksl[base],     bl1 = Ksl[base + 4];
                mma16h(s[nt], qh[ks], bh0, bh1);
                mma16h(s[nt], qh[ks], bl0, bl1);
                mma16h(s[nt], ql[ks], bh0, bh1);
            }
        }
        #pragma unroll
        for (int nt = 0; nt < 8; nt++) {
            int base = nt * 288 + kb + 32;
            unsigned b  = Ksh[base];
            unsigned bl = Ksl[base];
            mma8h(s[nt], q8h, b);
            mma8h(s[nt], q8h, bl);
            mma8h(s[nt], q8l, b);
        }

        // ---- online softmax (rows arow, arow+8) ----
        float mt0 = s[0][0], mt1 = s[0][2];
        #pragma unroll
        for (int nt = 0; nt < 8; nt++) {
            mt0 = fmaxf(mt0, fmaxf(s[nt][0], s[nt][1]));
            mt1 = fmaxf(mt1, fmaxf(s[nt][2], s[nt][3]));
        }
        mt0 = fmaxf(mt0, __shfl_xor_sync(0xffffffffu, mt0, 1));
        mt0 = fmaxf(mt0, __shfl_xor_sync(0xffffffffu, mt0, 2));
        mt1 = fmaxf(mt1, __shfl_xor_sync(0xffffffffu, mt1, 1));
        mt1 = fmaxf(mt1, __shfl_xor_sync(0xffffffffu, mt1, 2));
        float nm0 = fmaxf(m0, mt0), nm1 = fmaxf(m1, mt1);
        float c0 = __expf(m0 - nm0), c1 = __expf(m1 - nm1);
        float ls0 = 0.f, ls1 = 0.f;
        #pragma unroll
        for (int nt = 0; nt < 8; nt++) {
            s[nt][0] = __expf(s[nt][0] - nm0); ls0 += s[nt][0];
            s[nt][1] = __expf(s[nt][1] - nm0); ls0 += s[nt][1];
            s[nt][2] = __expf(s[nt][2] - nm1); ls1 += s[nt][2];
            s[nt][3] = __expf(s[nt][3] - nm1); ls1 += s[nt][3];
        }
        ls0 += __shfl_xor_sync(0xffffffffu, ls0, 1);
        ls0 += __shfl_xor_sync(0xffffffffu, ls0, 2);
        ls1 += __shfl_xor_sync(0xffffffffu, ls1, 1);
        ls1 += __shfl_xor_sync(0xffffffffu, ls1, 2);
        l0 = l0 * c0 + ls0; m0 = nm0;
        l1 = l1 * c1 + ls1; m1 = nm1;
        #pragma unroll
        for (int nt = 0; nt < 9; nt++) {
            o[nt][0] *= c0; o[nt][1] *= c0;
            o[nt][2] *= c1; o[nt][3] *= c1;
        }

        // ---- publish P (fp16 hi/lo, key-paired half2), warp-private rows ----
        __syncwarp();
        #pragma unroll
        for (int nt = 0; nt < 8; nt++) {
            unsigned ph, pl;
            split2(s[nt][0], s[nt][1], ph, pl);
            Ph[(arow)     * 36 + 4 * nt + tg] = ph;
            Pl[(arow)     * 36 + 4 * nt + tg] = pl;
            split2(s[nt][2], s[nt][3], ph, pl);
            Ph[(arow + 8) * 36 + 4 * nt + tg] = ph;
            Pl[(arow + 8) * 36 + 4 * nt + tg] = pl;
        }
        __syncwarp();

        // ---- O += P @ V (fp16x3; V converted per-use) ----
        #pragma unroll
        for (int ks = 0; ks < 4; ks++) {
            unsigned ah[4], al[4];
            ah[0] = Ph[(arow)     * 36 + 8 * ks + tg];
            ah[1] = Ph[(arow + 8) * 36 + 8 * ks + tg];
            ah[2] = Ph[(arow)     * 36 + 8 * ks + tg + 4];
            ah[3] = Ph[(arow + 8) * 36 + 8 * ks + tg + 4];
            al[0] = Pl[(arow)     * 36 + 8 * ks + tg];
            al[1] = Pl[(arow + 8) * 36 + 8 * ks + tg];
            al[2] = Pl[(arow)     * 36 + 8 * ks + tg + 4];
            al[3] = Pl[(arow + 8) * 36 + 8 * ks + tg + 4];
            const int vr = 16 * ks + 2 * tg;
            #pragma unroll
            for (int nt = 0; nt < 9; nt++) {
                int nc = nt * 8 + g;
                float v0 = Vs[(vr)     * 76 + nc];
                float v1 = Vs[(vr + 1) * 76 + nc];
                float v2 = Vs[(vr + 8) * 76 + nc];
                float v3 = Vs[(vr + 9) * 76 + nc];
                unsigned bh0, bl0, bh1, bl1;
                split2(v0, v1, bh0, bl0);
                split2(v2, v3, bh1, bl1);
                mma16h(o[nt], ah, bh0, bh1);
                mma16h(o[nt], ah, bl0, bl1);
                mma16h(o[nt], al, bh0, bh1);
            }
        }
    }

    // ---- epilogue ----
    float inv0 = 1.f / l0, inv1 = 1.f / l1;
    #pragma unroll
    for (int nt = 0; nt < 9; nt++) {
        int c = hoff + nt * 8 + 2 * tg;
        int r = q0 + arow;
        float2 v0 = make_float2(o[nt][0] * inv0, o[nt][1] * inv0);
        float2 v1 = make_float2(o[nt][2] * inv1, o[nt][3] * inv1);
        *(float2*)(O + (size_t)r * PROJ + c)       = v0;
        *(float2*)(O + (size_t)(r + 8) * PROJ + c) = v1;
    }
}

// ---------------------------------------------------------------------------
extern "C" void kernel_launch(void* const* d_in, const int* in_sizes, int n_in,
                              void* d_out, int out_size)
{
    const float* hidden = (const float*)d_in[0];
    const float* cosp   = (const float*)d_in[1];
    const float* sinp   = (const float*)d_in[2];
    const float* Wq     = (const float*)d_in[3];
    const float* Wk     = (const float*)d_in[4];
    const float* Wv     = (const float*)d_in[5];
    const float* Wo     = (const float*)d_in[6];
    const float* qsc    = (const float*)d_in[7];
    const float* ksc    = (const float*)d_in[8];
    float* out = (float*)d_out;

    float *q, *k, *v, *o;
    cudaGetSymbolAddress((void**)&q, g_q);
    cudaGetSymbolAddress((void**)&k, g_k);
    cudaGetSymbolAddress((void**)&v, g_v);
    cudaGetSymbolAddress((void**)&o, g_o);

    dim3 gq(PROJ / 128, N_TOK / 128, 3);
    gemm_x3_kernel<<<gq, 256>>>(hidden, Wq, q, Wk, k, Wv, v, N_TOK, PROJ, HIDDEN);

    normrope_kernel<<<(N_TOK * NUM_HEADS) / 8, 256>>>(cosp, sinp, qsc, ksc);

    cudaFuncSetAttribute(attn_h3_kernel,
                         cudaFuncAttributeMaxDynamicSharedMemorySize,
                         ATTN_SMEM_BYTES);
    attn_h3_kernel<<<dim3(NUM_HEADS, N_TOK / 128), 256, ATTN_SMEM_BYTES>>>(q, k, v, o);

    dim3 go(HIDDEN / 128, N_TOK / 128, 1);
    gemm_x3_kernel<<<go, 256>>>(o, Wo, out, Wo, out, Wo, out, N_TOK, HIDDEN, PROJ);
}

// round 7
// speedup vs baseline: 2.7541x; 1.2108x over previous
#include <cuda_runtime.h>
#include <cuda_fp16.h>
#include <math.h>

#define N_TOK     4096
#define HIDDEN    1152
#define NUM_HEADS 16
#define HEAD_DIM  72
#define PROJ      1152   // NUM_HEADS * HEAD_DIM

// Scratch (device globals: allocation-free per harness rules)
__device__ float g_q[(size_t)N_TOK * PROJ];
__device__ float g_k[(size_t)N_TOK * PROJ];
__device__ float g_v[(size_t)N_TOK * PROJ];
__device__ float g_o[(size_t)N_TOK * PROJ];

// ---------------------------------------------------------------------------
// tf32 helpers (GEMM path)
// ---------------------------------------------------------------------------
__device__ __forceinline__ unsigned f2tf(float x) {
    unsigned u;
    asm("cvt.rna.tf32.f32 %0, %1;" : "=r"(u) : "f"(x));
    return u;
}
__device__ __forceinline__ float uif(unsigned u) { return __uint_as_float(u); }

__device__ __forceinline__ void mma8(float c[4], const unsigned a[4], const unsigned b[2]) {
    asm("mma.sync.aligned.m16n8k8.row.col.f32.tf32.tf32.f32 "
        "{%0,%1,%2,%3},{%4,%5,%6,%7},{%8,%9},{%0,%1,%2,%3};"
        : "+f"(c[0]), "+f"(c[1]), "+f"(c[2]), "+f"(c[3])
        : "r"(a[0]), "r"(a[1]), "r"(a[2]), "r"(a[3]), "r"(b[0]), "r"(b[1]));
}

// ---------------------------------------------------------------------------
// fp16 helpers (attention path)
// ---------------------------------------------------------------------------
__device__ __forceinline__ unsigned packh2(float lo, float hi) {
    unsigned r;
    asm("cvt.rn.f16x2.f32 %0, %1, %2;" : "=r"(r) : "f"(hi), "f"(lo));
    return r;
}
__device__ __forceinline__ float2 h22f(unsigned u) {
    __half2 h = *reinterpret_cast<__half2*>(&u);
    return __half22float2(h);
}
__device__ __forceinline__ void split2(float a, float b, unsigned &h, unsigned &l) {
    h = packh2(a, b);
    float2 f = h22f(h);
    l = packh2(a - f.x, b - f.y);
}

__device__ __forceinline__ void mma16h(float c[4], const unsigned a[4],
                                       unsigned b0, unsigned b1) {
    asm("mma.sync.aligned.m16n8k16.row.col.f32.f16.f16.f32 "
        "{%0,%1,%2,%3},{%4,%5,%6,%7},{%8,%9},{%0,%1,%2,%3};"
        : "+f"(c[0]), "+f"(c[1]), "+f"(c[2]), "+f"(c[3])
        : "r"(a[0]), "r"(a[1]), "r"(a[2]), "r"(a[3]), "r"(b0), "r"(b1));
}
__device__ __forceinline__ void mma8h(float c[4], const unsigned a[2], unsigned b0) {
    asm("mma.sync.aligned.m16n8k8.row.col.f32.f16.f16.f32 "
        "{%0,%1,%2,%3},{%4,%5},{%6},{%0,%1,%2,%3};"
        : "+f"(c[0]), "+f"(c[1]), "+f"(c[2]), "+f"(c[3])
        : "r"(a[0]), "r"(a[1]), "r"(b0));
}

// cp.async 16B
__device__ __forceinline__ void cp16(void* smem_dst, const void* gsrc) {
    unsigned s = (unsigned)__cvta_generic_to_shared(smem_dst);
    asm volatile("cp.async.cg.shared.global [%0], [%1], 16;" :: "r"(s), "l"(gsrc));
}
#define CP_COMMIT() asm volatile("cp.async.commit_group;" ::: "memory")
#define CP_WAIT0()  asm volatile("cp.async.wait_group 0;" ::: "memory")

// ---------------------------------------------------------------------------
// tf32x3 GEMM with 2-stage smem double buffering (unchanged).
// ---------------------------------------------------------------------------
__global__ void __launch_bounds__(256) gemm_x3_kernel(
    const float* __restrict__ A,
    const float* __restrict__ B0, float* __restrict__ C0,
    const float* __restrict__ B1, float* __restrict__ C1,
    const float* __restrict__ B2, float* __restrict__ C2,
    int M, int N, int K)
{
    __shared__ unsigned Ah[2][8][136], Al[2][8][136];
    __shared__ unsigned Bh[2][8][136], Bl[2][8][136];

    const float* B = (blockIdx.z == 0) ? B0 : (blockIdx.z == 1) ? B1 : B2;
    float*       C = (blockIdx.z == 0) ? C0 : (blockIdx.z == 1) ? C1 : C2;

    const int tid  = threadIdx.x;
    const int lane = tid & 31;
    const int wid  = tid >> 5;
    const int row0 = blockIdx.y * 128;
    const int col0 = blockIdx.x * 128;
    const int warpM = (wid & 1) * 64;
    const int warpN = (wid >> 1) * 32;
    const int g  = lane >> 2;
    const int tg = lane & 3;

    const int aRow = tid >> 1;
    const int aC   = (tid & 1) * 4;
    const int bRow = tid >> 5;
    const int bC   = (tid & 31) * 4;

    float acc[4][4][4];
    #pragma unroll
    for (int mt = 0; mt < 4; mt++)
        #pragma unroll
        for (int nt = 0; nt < 4; nt++)
            #pragma unroll
            for (int r = 0; r < 4; r++) acc[mt][nt][r] = 0.f;

    float4 a4 = *(const float4*)(A + (size_t)(row0 + aRow) * K + aC);
    float4 b4 = *(const float4*)(B + (size_t)bRow * N + col0 + bC);
    {
        float av[4] = {a4.x, a4.y, a4.z, a4.w};
        #pragma unroll
        for (int j = 0; j < 4; j++) {
            unsigned hh = f2tf(av[j]);
            Ah[0][aC + j][aRow] = hh;
            Al[0][aC + j][aRow] = f2tf(av[j] - uif(hh));
        }
        float bv[4] = {b4.x, b4.y, b4.z, b4.w};
        uint4 hh, ll;
        unsigned* hp = &hh.x; unsigned* lp = &ll.x;
        #pragma unroll
        for (int j = 0; j < 4; j++) {
            unsigned hv = f2tf(bv[j]);
            hp[j] = hv;
            lp[j] = f2tf(bv[j] - uif(hv));
        }
        *(uint4*)&Bh[0][bRow][bC] = hh;
        *(uint4*)&Bl[0][bRow][bC] = ll;
    }
    __syncthreads();

    int cur = 0;
    for (int k0 = 0; k0 < K; k0 += 8) {
        const bool more = (k0 + 8 < K);
        if (more) {
            a4 = *(const float4*)(A + (size_t)(row0 + aRow) * K + (k0 + 8) + aC);
            b4 = *(const float4*)(B + (size_t)(k0 + 8 + bRow) * N + col0 + bC);
        }

        unsigned ah[4][4], al[4][4], bh[4][2], bl[4][2];
        #pragma unroll
        for (int mt = 0; mt < 4; mt++) {
            int m = warpM + mt * 16 + g;
            ah[mt][0] = Ah[cur][tg][m];     ah[mt][1] = Ah[cur][tg][m + 8];
            ah[mt][2] = Ah[cur][tg + 4][m]; ah[mt][3] = Ah[cur][tg + 4][m + 8];
            al[mt][0] = Al[cur][tg][m];     al[mt][1] = Al[cur][tg][m + 8];
            al[mt][2] = Al[cur][tg + 4][m]; al[mt][3] = Al[cur][tg + 4][m + 8];
        }
        #pragma unroll
        for (int nt = 0; nt < 4; nt++) {
            int n = warpN + nt * 8 + g;
            bh[nt][0] = Bh[cur][tg][n]; bh[nt][1] = Bh[cur][tg + 4][n];
            bl[nt][0] = Bl[cur][tg][n]; bl[nt][1] = Bl[cur][tg + 4][n];
        }
        #pragma unroll
        for (int mt = 0; mt < 4; mt++)
            #pragma unroll
            for (int nt = 0; nt < 4; nt++) {
                mma8(acc[mt][nt], ah[mt], bh[nt]);
                mma8(acc[mt][nt], ah[mt], bl[nt]);
                mma8(acc[mt][nt], al[mt], bh[nt]);
            }

        if (more) {
            int nxt = cur ^ 1;
            float av[4] = {a4.x, a4.y, a4.z, a4.w};
            #pragma unroll
            for (int j = 0; j < 4; j++) {
                unsigned hh = f2tf(av[j]);
                Ah[nxt][aC + j][aRow] = hh;
                Al[nxt][aC + j][aRow] = f2tf(av[j] - uif(hh));
            }
            float bv[4] = {b4.x, b4.y, b4.z, b4.w};
            uint4 hh, ll;
            unsigned* hp = &hh.x; unsigned* lp = &ll.x;
            #pragma unroll
            for (int j = 0; j < 4; j++) {
                unsigned hv = f2tf(bv[j]);
                hp[j] = hv;
                lp[j] = f2tf(bv[j] - uif(hv));
            }
            *(uint4*)&Bh[nxt][bRow][bC] = hh;
            *(uint4*)&Bl[nxt][bRow][bC] = ll;
            __syncthreads();
            cur = nxt;
        }
    }

    #pragma unroll
    for (int mt = 0; mt < 4; mt++)
        #pragma unroll
        for (int nt = 0; nt < 4; nt++) {
            int r = row0 + warpM + mt * 16 + g;
            int c = col0 + warpN + nt * 8 + 2 * tg;
            float2 v0 = make_float2(acc[mt][nt][0], acc[mt][nt][1]);
            float2 v1 = make_float2(acc[mt][nt][2], acc[mt][nt][3]);
            *(float2*)(C + (size_t)r * N + c)       = v0;
            *(float2*)(C + (size_t)(r + 8) * N + c) = v1;
        }
}

// ---------------------------------------------------------------------------
// Fused RMSNorm + 2D RoPE (unchanged)
// ---------------------------------------------------------------------------
__device__ __forceinline__ float warp_sum(float v) {
    #pragma unroll
    for (int o = 16; o > 0; o >>= 1) v += __shfl_xor_sync(0xffffffffu, v, o);
    return v;
}

__global__ void __launch_bounds__(256) normrope_kernel(
    const float* __restrict__ cosp, const float* __restrict__ sinp,
    const float* __restrict__ qscale, const float* __restrict__ kscale)
{
    __shared__ float buf[8][72];
    const int warp = threadIdx.x >> 5;
    const int lane = threadIdx.x & 31;
    const int gw = blockIdx.x * 8 + warp;
    const int n = gw >> 4;
    const int h = gw & 15;
    const size_t off = (size_t)n * PROJ + h * HEAD_DIM;
    const float* crow = cosp + (size_t)n * HEAD_DIM;
    const float* srow = sinp + (size_t)n * HEAD_DIM;

    float* bufs[3] = { g_q + off, g_k + off, g_v + off };

    for (int w = 0; w < 3; w++) {
        float* p = bufs[w];
        float ss = 0.f;
        for (int d = lane; d < HEAD_DIM; d += 32) {
            float x = p[d];
            buf[warp][d] = x;
            ss += x * x;
        }
        ss = warp_sum(ss);
        float r = rsqrtf(ss * (1.f / HEAD_DIM) + 1e-6f);
        __syncwarp();
        for (int d = lane; d < HEAD_DIM; d += 32) {
            float y = buf[warp][d] * r;
            if (w == 0)      y *= qscale[d];
            else if (w == 1) y *= kscale[d];
            buf[warp][d] = y;
        }
        __syncwarp();
        if (w < 2) {
            for (int d = lane; d < HEAD_DIM; d += 32) {
                int j = (d < 36) ? d : d - 36;
                float rot = (j < 18) ? -buf[warp][d + 18] : buf[warp][d - 18];
                p[d] = buf[warp][d] * crow[d] + rot * srow[d];
            }
        } else {
            for (int d = lane; d < HEAD_DIM; d += 32) p[d] = buf[warp][d];
        }
        __syncwarp();
    }
}

// ---------------------------------------------------------------------------
// Flash attention, fp16x3 mma, cp.async-pipelined K/V tiles.
// Block = (head, 128-query tile), 8 warps; warp w owns S/O rows 16w..16w+15.
// Smem (u32 units, total 27904 = 109 KB):
//   Kraw [64][72] f32  (cp.async target)            4608
//   Vraw [64][72] f32  (cp.async target)            4608
//   Ksh/Ksl [64 keys][36 half2 d-pairs]             2304 each
//   Vth/Vtl [32 keypairs][72 d, stride 76]          2432 each
//   Ph/Pl  [128 rows][36 half2 key-pairs]           4608 each
//   Qs fp32 [128][72] aliases Ph+Pl (pre-loop only)
// ---------------------------------------------------------------------------
#define ATTN_SMEM_U32 27904
#define ATTN_SMEM_BYTES (ATTN_SMEM_U32 * 4)

__global__ void __launch_bounds__(256) attn_h3_kernel(
    const float* __restrict__ Q, const float* __restrict__ K,
    const float* __restrict__ V, float* __restrict__ O)
{
    extern __shared__ unsigned sm[];
    float*    Kraw = (float*)sm;              // 4608
    float*    Vraw = (float*)(sm + 4608);     // 4608
    unsigned* Ksh  = sm + 9216;               // 2304
    unsigned* Ksl  = sm + 11520;              // 2304
    unsigned* Vth  = sm + 13824;              // 2432
    unsigned* Vtl  = sm + 16256;              // 2432
    unsigned* Ph   = sm + 18688;              // 4608
    unsigned* Pl   = sm + 23296;              // 4608
    float*    Qs   = (float*)Ph;              // 9216 f32 alias

    const int h    = blockIdx.x;
    const int q0   = blockIdx.y * 128;
    const int tid  = threadIdx.x;
    const int lane = tid & 31;
    const int w    = tid >> 5;
    const int g    = lane >> 2;
    const int tg   = lane & 3;
    const int hoff = h * HEAD_DIM;
    const int arow = w * 16 + g;

    const float* Kh = K + hoff;
    const float* Vh = V + hoff;

    // ---- issue cp.async for tile 0 (overlaps Q staging) ----
    {
        #pragma unroll
        for (int ii = 0; ii < 9; ii++) {
            int it = tid + ii * 256;           // 0..2303
            int half = (it >= 1152);
            int i = it - half * 1152;
            int o = 4 * i, r = o / 72, d = o - r * 72;
            if (!half) cp16(Kraw + o, Kh + (size_t)r * PROJ + d);
            else       cp16(Vraw + o, Vh + (size_t)r * PROJ + d);
        }
        CP_COMMIT();
    }

    // ---- stage Q (fp32) ----
    for (int it = tid; it < 128 * 18; it += 256) {
        int r = it / 18, c = it - r * 18;
        float4 v = *(const float4*)(Q + (size_t)(q0 + r) * PROJ + hoff + 4 * c);
        *(float4*)&Qs[r * 72 + 4 * c] = v;
    }
    __syncthreads();

    // ---- extract Q fragments (hi/lo fp16), 4 k16 steps + 1 k8 tail ----
    unsigned qh[4][4], ql[4][4], q8h[2], q8l[2];
    #pragma unroll
    for (int ks = 0; ks < 4; ks++) {
        float2 x0 = *(float2*)&Qs[(arow)     * 72 + 16 * ks + 2 * tg];
        float2 x1 = *(float2*)&Qs[(arow + 8) * 72 + 16 * ks + 2 * tg];
        float2 x2 = *(float2*)&Qs[(arow)     * 72 + 16 * ks + 2 * tg + 8];
        float2 x3 = *(float2*)&Qs[(arow + 8) * 72 + 16 * ks + 2 * tg + 8];
        split2(x0.x, x0.y, qh[ks][0], ql[ks][0]);
        split2(x1.x, x1.y, qh[ks][1], ql[ks][1]);
        split2(x2.x, x2.y, qh[ks][2], ql[ks][2]);
        split2(x3.x, x3.y, qh[ks][3], ql[ks][3]);
    }
    {
        float2 x0 = *(float2*)&Qs[(arow)     * 72 + 64 + 2 * tg];
        float2 x1 = *(float2*)&Qs[(arow + 8) * 72 + 64 + 2 * tg];
        split2(x0.x, x0.y, q8h[0], q8l[0]);
        split2(x1.x, x1.y, q8h[1], q8l[1]);
    }

    float m0 = -1e30f, m1 = -1e30f, l0 = 0.f, l1 = 0.f;
    float o[9][4];
    #pragma unroll
    for (int nt = 0; nt < 9; nt++)
        #pragma unroll
        for (int r = 0; r < 4; r++) o[nt][r] = 0.f;

    const int kb = g * 36 + tg;

    for (int t = 0; t < N_TOK / 64; t++) {
        CP_WAIT0();
        __syncthreads();   // tile t raw visible; prior compute (K/V/P reads) done

        // ---- convert K raw -> fp16 hi/lo ----
        for (int it = tid; it < 1152; it += 256) {
            int r = it / 18, c = it - r * 18;
            float4 kv = *(float4*)&Kraw[r * 72 + 4 * c];
            unsigned h01, l01, h23, l23;
            split2(kv.x, kv.y, h01, l01);
            split2(kv.z, kv.w, h23, l23);
            *(uint2*)&Ksh[r * 36 + 2 * c] = make_uint2(h01, h23);
            *(uint2*)&Ksl[r * 36 + 2 * c] = make_uint2(l01, l23);
        }
        // ---- convert V raw -> fp16 hi/lo, key-pair packed [kp][d] ----
        for (int it = tid; it < 576; it += 256) {
            int kp = it / 18, c = it - kp * 18;
            float4 v0 = *(float4*)&Vraw[(2 * kp)     * 72 + 4 * c];
            float4 v1 = *(float4*)&Vraw[(2 * kp + 1) * 72 + 4 * c];
            uint4 hh, ll;
            split2(v0.x, v1.x, hh.x, ll.x);
            split2(v0.y, v1.y, hh.y, ll.y);
            split2(v0.z, v1.z, hh.z, ll.z);
            split2(v0.w, v1.w, hh.w, ll.w);
            *(uint4*)&Vth[kp * 76 + 4 * c] = hh;
            *(uint4*)&Vtl[kp * 76 + 4 * c] = ll;
        }
        __syncthreads();   // converted tiles ready; raw buffer free

        // ---- prefetch tile t+1 (hidden behind compute) ----
        if (t + 1 < N_TOK / 64) {
            const float* Kg = Kh + (size_t)(t + 1) * 64 * PROJ;
            const float* Vg = Vh + (size_t)(t + 1) * 64 * PROJ;
            #pragma unroll
            for (int ii = 0; ii < 9; ii++) {
                int it = tid + ii * 256;
                int half = (it >= 1152);
                int i = it - half * 1152;
                int oo = 4 * i, r = oo / 72, d = oo - r * 72;
                if (!half) cp16(Kraw + oo, Kg + (size_t)r * PROJ + d);
                else       cp16(Vraw + oo, Vg + (size_t)r * PROJ + d);
            }
            CP_COMMIT();
        }

        // ---- S = Q @ K^T (fp16x3) ----
        float s[8][4];
        #pragma unroll
        for (int nt = 0; nt < 8; nt++)
            #pragma unroll
            for (int r = 0; r < 4; r++) s[nt][r] = 0.f;

        #pragma unroll
        for (int ks = 0; ks < 4; ks++) {
            #pragma unroll
            for (int nt = 0; nt < 8; nt++) {
                int base = nt * 288 + kb + 8 * ks;
                unsigned bh0 = Ksh[base], bh1 = Ksh[base + 4];
                unsigned bl0 = Ksl[base], bl1 = Ksl[base + 4];
                mma16h(s[nt], qh[ks], bh0, bh1);
                mma16h(s[nt], qh[ks], bl0, bl1);
                mma16h(s[nt], ql[ks], bh0, bh1);
            }
        }
        #pragma unroll
        for (int nt = 0; nt < 8; nt++) {
            int base = nt * 288 + kb + 32;
            unsigned b  = Ksh[base];
            unsigned bl = Ksl[base];
            mma8h(s[nt], q8h, b);
            mma8h(s[nt], q8h, bl);
            mma8h(s[nt], q8l, b);
        }

        // ---- online softmax ----
        float mt0 = s[0][0], mt1 = s[0][2];
        #pragma unroll
        for (int nt = 0; nt < 8; nt++) {
            mt0 = fmaxf(mt0, fmaxf(s[nt][0], s[nt][1]));
            mt1 = fmaxf(mt1, fmaxf(s[nt][2], s[nt][3]));
        }
        mt0 = fmaxf(mt0, __shfl_xor_sync(0xffffffffu, mt0, 1));
        mt0 = fmaxf(mt0, __shfl_xor_sync(0xffffffffu, mt0, 2));
        mt1 = fmaxf(mt1, __shfl_xor_sync(0xffffffffu, mt1, 1));
        mt1 = fmaxf(mt1, __shfl_xor_sync(0xffffffffu, mt1, 2));
        float nm0 = fmaxf(m0, mt0), nm1 = fmaxf(m1, mt1);
        float c0 = __expf(m0 - nm0), c1 = __expf(m1 - nm1);
        float ls0 = 0.f, ls1 = 0.f;
        #pragma unroll
        for (int nt = 0; nt < 8; nt++) {
            s[nt][0] = __expf(s[nt][0] - nm0); ls0 += s[nt][0];
            s[nt][1] = __expf(s[nt][1] - nm0); ls0 += s[nt][1];
            s[nt][2] = __expf(s[nt][2] - nm1); ls1 += s[nt][2];
            s[nt][3] = __expf(s[nt][3] - nm1); ls1 += s[nt][3];
        }
        ls0 += __shfl_xor_sync(0xffffffffu, ls0, 1);
        ls0 += __shfl_xor_sync(0xffffffffu, ls0, 2);
        ls1 += __shfl_xor_sync(0xffffffffu, ls1, 1);
        ls1 += __shfl_xor_sync(0xffffffffu, ls1, 2);
        l0 = l0 * c0 + ls0; m0 = nm0;
        l1 = l1 * c1 + ls1; m1 = nm1;
        #pragma unroll
        for (int nt = 0; nt < 9; nt++) {
            o[nt][0] *= c0; o[nt][1] *= c0;
            o[nt][2] *= c1; o[nt][3] *= c1;
        }

        // ---- publish P (fp16 hi/lo, key-paired half2), warp-private rows ----
        __syncwarp();
        #pragma unroll
        for (int nt = 0; nt < 8; nt++) {
            unsigned ph, pl;
            split2(s[nt][0], s[nt][1], ph, pl);
            Ph[(arow)     * 36 + 4 * nt + tg] = ph;
            Pl[(arow)     * 36 + 4 * nt + tg] = pl;
            split2(s[nt][2], s[nt][3], ph, pl);
            Ph[(arow + 8) * 36 + 4 * nt + tg] = ph;
            Pl[(arow + 8) * 36 + 4 * nt + tg] = pl;
        }
        __syncwarp();

        // ---- O += P @ V (fp16x3, pre-converted V) ----
        #pragma unroll
        for (int ks = 0; ks < 4; ks++) {
            unsigned ah[4], al[4];
            ah[0] = Ph[(arow)     * 36 + 8 * ks + tg];
            ah[1] = Ph[(arow + 8) * 36 + 8 * ks + tg];
            ah[2] = Ph[(arow)     * 36 + 8 * ks + tg + 4];
            ah[3] = Ph[(arow + 8) * 36 + 8 * ks + tg + 4];
            al[0] = Pl[(arow)     * 36 + 8 * ks + tg];
            al[1] = Pl[(arow + 8) * 36 + 8 * ks + tg];
            al[2] = Pl[(arow)     * 36 + 8 * ks + tg + 4];
            al[3] = Pl[(arow + 8) * 36 + 8 * ks + tg + 4];
            const int kp0 = 8 * ks + tg;
            #pragma unroll
            for (int nt = 0; nt < 9; nt++) {
                int nc = nt * 8 + g;
                unsigned bh0 = Vth[(kp0)     * 76 + nc];
                unsigned bh1 = Vth[(kp0 + 4) * 76 + nc];
                unsigned bl0 = Vtl[(kp0)     * 76 + nc];
                unsigned bl1 = Vtl[(kp0 + 4) * 76 + nc];
                mma16h(o[nt], ah, bh0, bh1);
                mma16h(o[nt], ah, bl0, bl1);
                mma16h(o[nt], al, bh0, bh1);
            }
        }
    }

    // ---- epilogue ----
    float inv0 = 1.f / l0, inv1 = 1.f / l1;
    #pragma unroll
    for (int nt = 0; nt < 9; nt++) {
        int c = hoff + nt * 8 + 2 * tg;
        int r = q0 + arow;
        float2 v0 = make_float2(o[nt][0] * inv0, o[nt][1] * inv0);
        float2 v1 = make_float2(o[nt][2] * inv1, o[nt][3] * inv1);
        *(float2*)(O + (size_t)r * PROJ + c)       = v0;
        *(float2*)(O + (size_t)(r + 8) * PROJ + c) = v1;
    }
}

// ---------------------------------------------------------------------------
extern "C" void kernel_launch(void* const* d_in, const int* in_sizes, int n_in,
                              void* d_out, int out_size)
{
    const float* hidden = (const float*)d_in[0];
    const float* cosp   = (const float*)d_in[1];
    const float* sinp   = (const float*)d_in[2];
    const float* Wq     = (const float*)d_in[3];
    const float* Wk     = (const float*)d_in[4];
    const float* Wv     = (const float*)d_in[5];
    const float* Wo     = (const float*)d_in[6];
    const float* qsc    = (const float*)d_in[7];
    const float* ksc    = (const float*)d_in[8];
    float* out = (float*)d_out;

    float *q, *k, *v, *o;
    cudaGetSymbolAddress((void**)&q, g_q);
    cudaGetSymbolAddress((void**)&k, g_k);
    cudaGetSymbolAddress((void**)&v, g_v);
    cudaGetSymbolAddress((void**)&o, g_o);

    dim3 gq(PROJ / 128, N_TOK / 128, 3);
    gemm_x3_kernel<<<gq, 256>>>(hidden, Wq, q, Wk, k, Wv, v, N_TOK, PROJ, HIDDEN);

    normrope_kernel<<<(N_TOK * NUM_HEADS) / 8, 256>>>(cosp, sinp, qsc, ksc);

    cudaFuncSetAttribute(attn_h3_kernel,
                         cudaFuncAttributeMaxDynamicSharedMemorySize,
                         ATTN_SMEM_BYTES);
    attn_h3_kernel<<<dim3(NUM_HEADS, N_TOK / 128), 256, ATTN_SMEM_BYTES>>>(q, k, v, o);

    dim3 go(HIDDEN / 128, N_TOK / 128, 1);
    gemm_x3_kernel<<<go, 256>>>(o, Wo, out, Wo, out, Wo, out, N_TOK, HIDDEN, PROJ);
}